// round 14
// baseline (speedup 1.0000x reference)
#include <cuda_runtime.h>
#include <cuda_bf16.h>
#include <cuda_fp16.h>
#include <math.h>
#include <stdint.h>

#define N_CNT 10000
#define E_CNT 30000
#define D_IN 64
#define EDIM 16
#define H1 128
#define H2 64
#define C_OUT 10

#define NB1 1088
#define NB2 170

#define MPAD 10112  // 79*128
#define NPAD 1152   // 9*128
#define KSPLIT 128  // single fp16 term: Ah x Bh

// ---------------- scratch ----------------------------------------------------
__device__ int   g_src[E_CNT];
__device__ int   g_dst[E_CNT];
__device__ float g_B2[H2 * NB2];
__device__ float g_h [N_CNT * H1];
__device__ __half g_Ab[(size_t)MPAD * KSPLIT];
__device__ __half g_Bb[(size_t)NPAD * KSPLIT];
__device__ __half g_P1[(size_t)N_CNT * NB1];
__device__ float g_agg1[N_CNT * H2];
__device__ float g_h2 [N_CNT * H2];
__device__ __half g_P2[(size_t)N_CNT * NB2];
__device__ float g_agg2[N_CNT * C_OUT];

// ---------------- helpers ----------------------------------------------------
__device__ __forceinline__ uint32_t smem_u32(const void* p) {
    uint32_t a;
    asm("{ .reg .u64 t; cvta.to.shared.u64 t, %1; cvt.u32.u64 %0, t; }"
        : "=r"(a) : "l"(p));
    return a;
}
__device__ __forceinline__ void ldmat_x4(uint32_t& r0, uint32_t& r1,
                                         uint32_t& r2, uint32_t& r3, uint32_t a) {
    asm volatile("ldmatrix.sync.aligned.m8n8.x4.shared.b16 {%0,%1,%2,%3}, [%4];"
                 : "=r"(r0), "=r"(r1), "=r"(r2), "=r"(r3) : "r"(a));
}
__device__ __forceinline__ void mma_f16(float* c, const uint32_t* a,
                                        const uint32_t* b) {
    asm volatile(
        "mma.sync.aligned.m16n8k16.row.col.f32.f16.f16.f32 "
        "{%0,%1,%2,%3}, {%4,%5,%6,%7}, {%8,%9}, {%0,%1,%2,%3};"
        : "+f"(c[0]), "+f"(c[1]), "+f"(c[2]), "+f"(c[3])
        : "r"(a[0]), "r"(a[1]), "r"(a[2]), "r"(a[3]), "r"(b[0]), "r"(b[1]));
}
__device__ __forceinline__ void cp16(uint32_t dst, const void* src) {
    asm volatile("cp.async.cg.shared.global [%0], [%1], 16;"
                 :: "r"(dst), "l"(src));
}
#define CP_COMMIT() asm volatile("cp.async.commit_group;" ::: "memory")
#define CP_WAIT0()  asm volatile("cp.async.wait_group 0;" ::: "memory")

__device__ __forceinline__ void fma8_u4(float* acc, uint4 raw, float w) {
    __half2 h0 = *reinterpret_cast<__half2*>(&raw.x);
    __half2 h1 = *reinterpret_cast<__half2*>(&raw.y);
    __half2 h2 = *reinterpret_cast<__half2*>(&raw.z);
    __half2 h3 = *reinterpret_cast<__half2*>(&raw.w);
    float2 f0 = __half22float2(h0), f1 = __half22float2(h1);
    float2 f2 = __half22float2(h2), f3 = __half22float2(h3);
    acc[0] = fmaf(w, f0.x, acc[0]); acc[1] = fmaf(w, f0.y, acc[1]);
    acc[2] = fmaf(w, f1.x, acc[2]); acc[3] = fmaf(w, f1.y, acc[3]);
    acc[4] = fmaf(w, f2.x, acc[4]); acc[5] = fmaf(w, f2.y, acc[5]);
    acc[6] = fmaf(w, f3.x, acc[6]); acc[7] = fmaf(w, f3.y, acc[7]);
}

// ---------------- launch 0: prep (idx + B1' + B2) ----------------------------
#define PR_O1 (E_CNT)
#define PR_O2 (PR_O1 + NPAD * H1)
#define PR_TOT (PR_O2 + H2 * NB2)

__global__ void prep_all(const void* eidx,
                         const float* __restrict__ We1,
                         const float* __restrict__ be1,
                         const float* __restrict__ We2,
                         const float* __restrict__ be2) {
    int idx = blockIdx.x * blockDim.x + threadIdx.x;
    if (idx >= PR_TOT) return;
    if (idx < PR_O1) {
        const int* p = (const int*)eidx;
        bool is64 = true;
#pragma unroll
        for (int j = 0; j < 8; j++) is64 &= (p[2 * j + 1] == 0);
        if (is64) {
            const long long* q = (const long long*)eidx;
            g_src[idx] = (int)q[idx];
            g_dst[idx] = (int)q[E_CNT + idx];
        } else {
            g_src[idx] = p[idx];
            g_dst[idx] = p[E_CNT + idx];
        }
    } else if (idx < PR_O2) {
        int t = idx - PR_O1;
        int n = t / H1, k = t - n * H1;
        float v = 0.f;
        if (n < EDIM * H2) {
            int ke = n >> 6, o = n & 63;
            v = We1[(size_t)ke * (H1 * H2) + k * H2 + o];
        } else if (n < NB1) {
            v = be1[(size_t)k * H2 + (n - EDIM * H2)];
        }
        g_Bb[(size_t)n * KSPLIT + k] = __float2half_rn(v);
    } else {
        int t = idx - PR_O2;
        int i = t / NB2, col = t - i * NB2;
        float v;
        if (col < EDIM * C_OUT) {
            int k = col / C_OUT, c = col - k * C_OUT;
            v = We2[(size_t)k * (H2 * C_OUT) + i * C_OUT + c];
        } else {
            v = be2[(size_t)i * C_OUT + (col - EDIM * C_OUT)];
        }
        g_B2[t] = v;
    }
}

// ---------------- gemm_h: h=relu(x@W1+b1) + fp16 epilogue --------------------
#define HPAD_W 132
#define HPAD_A 68
#define GH_SMEM ((64 * HPAD_W + 64 * HPAD_A) * 4)

__global__ __launch_bounds__(256, 2)
void gemm_h(const float* __restrict__ x, const float* __restrict__ W1,
            const float* __restrict__ b1) {
    extern __shared__ float fsm[];
    float* Ws = fsm;
    float* As = fsm + 64 * HPAD_W;
    int tid = threadIdx.x;
    int tx = tid & 31, ty = tid >> 5;
    int m0 = blockIdx.x * 64;

    for (int i = tid; i < 2048; i += 256) {
        int k = i >> 5, n4 = (i & 31) * 4;
        float4 v = *reinterpret_cast<const float4*>(&W1[k * H1 + n4]);
        *reinterpret_cast<float4*>(&Ws[k * HPAD_W + n4]) = v;
    }
    for (int i = tid; i < 1024; i += 256) {
        int m = i >> 4, k4 = (i & 15) * 4;
        float4 v = (m0 + m < N_CNT)
            ? *reinterpret_cast<const float4*>(&x[(size_t)(m0 + m) * D_IN + k4])
            : make_float4(0.f, 0.f, 0.f, 0.f);
        As[(k4 + 0) * HPAD_A + m] = v.x;
        As[(k4 + 1) * HPAD_A + m] = v.y;
        As[(k4 + 2) * HPAD_A + m] = v.z;
        As[(k4 + 3) * HPAD_A + m] = v.w;
    }
    __syncthreads();

    float acc[8][4];
#pragma unroll
    for (int r = 0; r < 8; r++)
#pragma unroll
        for (int s = 0; s < 4; s++) acc[r][s] = 0.f;

#pragma unroll 4
    for (int k = 0; k < 64; k++) {
        float4 a0 = *reinterpret_cast<const float4*>(&As[k * HPAD_A + ty * 8]);
        float4 a1 = *reinterpret_cast<const float4*>(&As[k * HPAD_A + ty * 8 + 4]);
        float4 w  = *reinterpret_cast<const float4*>(&Ws[k * HPAD_W + tx * 4]);
        float a[8] = {a0.x, a0.y, a0.z, a0.w, a1.x, a1.y, a1.z, a1.w};
        float ww[4] = {w.x, w.y, w.z, w.w};
#pragma unroll
        for (int r = 0; r < 8; r++)
#pragma unroll
            for (int s = 0; s < 4; s++)
                acc[r][s] = fmaf(a[r], ww[s], acc[r][s]);
    }

    float bv[4];
#pragma unroll
    for (int s = 0; s < 4; s++) bv[s] = b1[tx * 4 + s];

#pragma unroll
    for (int r = 0; r < 8; r++) {
        int m = m0 + ty * 8 + r;
        float v[4];
#pragma unroll
        for (int s = 0; s < 4; s++) v[s] = fmaxf(acc[r][s] + bv[s], 0.f);
        if (m < N_CNT)
            *reinterpret_cast<float4*>(&g_h[(size_t)m * H1 + tx * 4]) =
                make_float4(v[0], v[1], v[2], v[3]);
        __half ah[4];
#pragma unroll
        for (int s = 0; s < 4; s++) ah[s] = __float2half_rn(v[s]);
        uint32_t hi0 = ((uint32_t)__half_as_ushort(ah[1]) << 16) |
                       __half_as_ushort(ah[0]);
        uint32_t hi1 = ((uint32_t)__half_as_ushort(ah[3]) << 16) |
                       __half_as_ushort(ah[2]);
        *reinterpret_cast<uint2*>(&g_Ab[(size_t)m * KSPLIT + tx * 4]) =
            make_uint2(hi0, hi1);
    }
}

// ---------------- mma fp16 GEMM, K=128 single stage --------------------------
#define SSTR 136
#define MMA_SMEM (2 * 128 * SSTR * 2)

__global__ __launch_bounds__(256, 2)
void mma_gemm_p1() {
    extern __shared__ __half sm[];
    __half* As = sm;
    __half* Bs = sm + 128 * SSTR;

    int tid = threadIdx.x;
    int wid = tid >> 5, lane = tid & 31;
    int row0 = blockIdx.y * 128;
    int col0 = blockIdx.x * 128;
    int wm0 = (wid >> 2) * 64;
    int wn0 = (wid & 3) * 32;

    int lrow = tid >> 1;
    int lq   = (tid & 1) * 8;
    const char* Ag = (const char*)(g_Ab) + (size_t)(row0 + lrow) * (KSPLIT * 2);
    const char* Bg = (const char*)(g_Bb) + (size_t)(col0 + lrow) * (KSPLIT * 2);
    uint32_t As_base = smem_u32(As);
    uint32_t Bs_base = smem_u32(Bs);
    uint32_t a_st = As_base + (uint32_t)(lrow * SSTR + lq * 8) * 2;
    uint32_t b_st = Bs_base + (uint32_t)(lrow * SSTR + lq * 8) * 2;

#pragma unroll
    for (int t = 0; t < 8; t++) {
        cp16(a_st + t * 16, Ag + (lq + t) * 16);
        cp16(b_st + t * 16, Bg + (lq + t) * 16);
    }
    CP_COMMIT();

    float acc[4][4][4];
#pragma unroll
    for (int i = 0; i < 4; i++)
#pragma unroll
        for (int j = 0; j < 4; j++)
#pragma unroll
            for (int q = 0; q < 4; q++) acc[i][j][q] = 0.f;

    int a_r = wm0 + (lane & 7) + ((lane >> 3) & 1) * 8;
    int a_c = ((lane >> 4) & 1) * 8;
    int b_r = wn0 + (lane & 7) + ((lane >> 4) & 1) * 8;
    int b_c = ((lane >> 3) & 1) * 8;

    CP_WAIT0();
    __syncthreads();

#pragma unroll
    for (int ks = 0; ks < 8; ks++) {
        int k0 = ks * 16;
        uint32_t afr[4][4], bfr[4][2];
#pragma unroll
        for (int i = 0; i < 4; i++) {
            uint32_t addr = As_base + (uint32_t)((a_r + i * 16) * SSTR + k0 + a_c) * 2;
            ldmat_x4(afr[i][0], afr[i][1], afr[i][2], afr[i][3], addr);
        }
#pragma unroll
        for (int jp = 0; jp < 2; jp++) {
            uint32_t addr = Bs_base + (uint32_t)((b_r + jp * 16) * SSTR + k0 + b_c) * 2;
            ldmat_x4(bfr[jp * 2][0], bfr[jp * 2][1],
                     bfr[jp * 2 + 1][0], bfr[jp * 2 + 1][1], addr);
        }
#pragma unroll
        for (int i = 0; i < 4; i++)
#pragma unroll
            for (int j = 0; j < 4; j++)
                mma_f16(acc[i][j], afr[i], bfr[j]);
    }

    int erow = lane >> 2;
    int ecol = (lane & 3) * 2;
#pragma unroll
    for (int i = 0; i < 4; i++) {
        int mg0 = row0 + wm0 + i * 16 + erow;
#pragma unroll
        for (int j = 0; j < 4; j++) {
            int ng = col0 + wn0 + j * 8 + ecol;
            if (ng >= NB1) continue;
            if (mg0 < N_CNT)
                *reinterpret_cast<__half2*>(&g_P1[(size_t)mg0 * NB1 + ng]) =
                    __floats2half2_rn(acc[i][j][0], acc[i][j][1]);
            if (mg0 + 8 < N_CNT)
                *reinterpret_cast<__half2*>(&g_P1[(size_t)(mg0 + 8) * NB1 + ng]) =
                    __floats2half2_rn(acc[i][j][2], acc[i][j][3]);
        }
    }
}

// ---------------- edge pass 1 (8 thr/edge, uint4 fp16 loads) -----------------
__global__ void edge_pass1(const float* __restrict__ ea) {
    int le = threadIdx.x >> 3;              // 0..31 local edge
    int tq = threadIdx.x & 7;               // cols tq*8 .. tq*8+7
    int e  = blockIdx.x * 32 + le;
    __shared__ float sea[32][16];
    if (e < E_CNT) {
        float2 v = *reinterpret_cast<const float2*>(&ea[(size_t)e * EDIM + tq * 2]);
        sea[le][tq * 2] = v.x;
        sea[le][tq * 2 + 1] = v.y;
    }
    __syncthreads();
    if (e >= E_CNT) return;
    int s = g_src[e], d = g_dst[e];
    const __half* Prow = g_P1 + (size_t)s * NB1 + tq * 8;
    float acc[8];
    {
        uint4 raw = *reinterpret_cast<const uint4*>(Prow + EDIM * H2);  // be1 part
        __half2 h0 = *reinterpret_cast<__half2*>(&raw.x);
        __half2 h1 = *reinterpret_cast<__half2*>(&raw.y);
        __half2 h2 = *reinterpret_cast<__half2*>(&raw.z);
        __half2 h3 = *reinterpret_cast<__half2*>(&raw.w);
        float2 f0 = __half22float2(h0), f1 = __half22float2(h1);
        float2 f2 = __half22float2(h2), f3 = __half22float2(h3);
        acc[0] = f0.x; acc[1] = f0.y; acc[2] = f1.x; acc[3] = f1.y;
        acc[4] = f2.x; acc[5] = f2.y; acc[6] = f3.x; acc[7] = f3.y;
    }
#pragma unroll
    for (int k = 0; k < EDIM; k++) {
        float w = sea[le][k];
        uint4 raw = *reinterpret_cast<const uint4*>(Prow + k * H2);
        fma8_u4(acc, raw, w);
    }
    float* dst = &g_agg1[(size_t)d * H2 + tq * 8];
#pragma unroll
    for (int q = 0; q < 8; q++) atomicAdd(dst + q, acc[q]);
}

// ---------------- gemm_h2 ----------------------------------------------------
#define GH2_RS 68
#define GH2_AS 68
#define GH2_SMEM ((128 * GH2_RS + 128 * GH2_AS) * 4)

__global__ __launch_bounds__(256, 2)
void gemm_h2(const float* __restrict__ root1, const float* __restrict__ bias1) {
    extern __shared__ float s2[];
    float* rs = s2;
    float* as = s2 + 128 * GH2_RS;
    int tid = threadIdx.x;
    int tx = tid & 15, ty = tid >> 4;
    int m0 = blockIdx.x * 64;

    for (int i = tid; i < 2048; i += 256) {
        int k = i >> 4, n4 = (i & 15) * 4;
        *reinterpret_cast<float4*>(&rs[k * GH2_RS + n4]) =
            *reinterpret_cast<const float4*>(&root1[k * H2 + n4]);
    }
    for (int i = tid; i < 2048; i += 256) {
        int m = i >> 5, k4 = (i & 31) * 4;
        float4 v = (m0 + m < N_CNT)
            ? *reinterpret_cast<const float4*>(&g_h[(size_t)(m0 + m) * H1 + k4])
            : make_float4(0.f, 0.f, 0.f, 0.f);
        as[(k4 + 0) * GH2_AS + m] = v.x;
        as[(k4 + 1) * GH2_AS + m] = v.y;
        as[(k4 + 2) * GH2_AS + m] = v.z;
        as[(k4 + 3) * GH2_AS + m] = v.w;
    }
    __syncthreads();

    float acc[4][4];
#pragma unroll
    for (int r = 0; r < 4; r++)
#pragma unroll
        for (int s = 0; s < 4; s++) acc[r][s] = 0.f;
#pragma unroll 4
    for (int k = 0; k < 128; k++) {
        float4 a4 = *reinterpret_cast<const float4*>(&as[k * GH2_AS + ty * 4]);
        float4 w4 = *reinterpret_cast<const float4*>(&rs[k * GH2_RS + tx * 4]);
        float a[4] = {a4.x, a4.y, a4.z, a4.w};
        float w[4] = {w4.x, w4.y, w4.z, w4.w};
#pragma unroll
        for (int r = 0; r < 4; r++)
#pragma unroll
            for (int s = 0; s < 4; s++)
                acc[r][s] = fmaf(a[r], w[s], acc[r][s]);
    }
    float bv[4];
#pragma unroll
    for (int s = 0; s < 4; s++) bv[s] = bias1[tx * 4 + s];
#pragma unroll
    for (int r = 0; r < 4; r++) {
        int m = m0 + ty * 4 + r;
        if (m >= N_CNT) continue;
        float4 ag = *reinterpret_cast<const float4*>(&g_agg1[(size_t)m * H2 + tx * 4]);
        float v0 = fmaxf(acc[r][0] + bv[0] + ag.x, 0.f);
        float v1 = fmaxf(acc[r][1] + bv[1] + ag.y, 0.f);
        float v2 = fmaxf(acc[r][2] + bv[2] + ag.z, 0.f);
        float v3 = fmaxf(acc[r][3] + bv[3] + ag.w, 0.f);
        *reinterpret_cast<float4*>(&g_h2[(size_t)m * H2 + tx * 4]) =
            make_float4(v0, v1, v2, v3);
    }
}

// ---------------- gemm_p2 (fp16 out) -----------------------------------------
#define GP2_HS 68
#define GP2_BS 172
#define GP2_SMEM ((64 * GP2_HS + 64 * GP2_BS) * 4)

__global__ __launch_bounds__(256, 2)
void gemm_p2() {
    extern __shared__ float s3[];
    float* h2t = s3;
    float* b2s = s3 + 64 * GP2_HS;
    int tid = threadIdx.x;
    int tx = tid & 15, ty = tid >> 4;
    int m0 = blockIdx.x * 64;

    for (int i = tid; i < 1024; i += 256) {
        int m = i >> 4, k4 = (i & 15) * 4;
        float4 v = (m0 + m < N_CNT)
            ? *reinterpret_cast<const float4*>(&g_h2[(size_t)(m0 + m) * H2 + k4])
            : make_float4(0.f, 0.f, 0.f, 0.f);
        h2t[(k4 + 0) * GP2_HS + m] = v.x;
        h2t[(k4 + 1) * GP2_HS + m] = v.y;
        h2t[(k4 + 2) * GP2_HS + m] = v.z;
        h2t[(k4 + 3) * GP2_HS + m] = v.w;
    }
    for (int i = tid; i < H2 * NB2; i += 256) {
        int k = i / NB2, c = i - k * NB2;
        b2s[k * GP2_BS + c] = g_B2[i];
    }
    __syncthreads();

#pragma unroll
    for (int p = 0; p < 3; p++) {
        int c0 = p * 64 + tx * 4;
        if (c0 >= NB2) break;
        float acc[4][4];
#pragma unroll
        for (int r = 0; r < 4; r++)
#pragma unroll
            for (int s = 0; s < 4; s++) acc[r][s] = 0.f;
#pragma unroll 4
        for (int k = 0; k < 64; k++) {
            float4 a4 = *reinterpret_cast<const float4*>(&h2t[k * GP2_HS + ty * 4]);
            float4 b4 = *reinterpret_cast<const float4*>(&b2s[k * GP2_BS + c0]);
            float a[4] = {a4.x, a4.y, a4.z, a4.w};
            float b[4] = {b4.x, b4.y, b4.z, b4.w};
#pragma unroll
            for (int r = 0; r < 4; r++)
#pragma unroll
                for (int s = 0; s < 4; s++)
                    acc[r][s] = fmaf(a[r], b[s], acc[r][s]);
        }
#pragma unroll
        for (int r = 0; r < 4; r++) {
            int m = m0 + ty * 4 + r;
            if (m >= N_CNT) continue;
            __half* dst = &g_P2[(size_t)m * NB2 + c0];
            if (c0 + 3 < NB2) {
                *reinterpret_cast<__half2*>(dst) =
                    __floats2half2_rn(acc[r][0], acc[r][1]);
                *reinterpret_cast<__half2*>(dst + 2) =
                    __floats2half2_rn(acc[r][2], acc[r][3]);
            } else {
#pragma unroll
                for (int s = 0; s < 4; s++)
                    if (c0 + s < NB2) dst[s] = __float2half_rn(acc[r][s]);
            }
        }
    }
}

// ---------------- edge pass 2 (fp16, half2, 5 thr/edge) ----------------------
__global__ void edge_pass2(const float* __restrict__ ea) {
    int t = blockIdx.x * blockDim.x + threadIdx.x;
    if (t >= E_CNT * 5) return;
    int e = t / 5, c2 = (t - (t / 5) * 5) * 2;
    int s = g_src[e], d = g_dst[e];
    const __half* Prow = g_P2 + (size_t)s * NB2;
    float2 acc;
    {
        __half2 h = *reinterpret_cast<const __half2*>(Prow + EDIM * C_OUT + c2);
        acc = __half22float2(h);
    }
    const float* eav = ea + (size_t)e * EDIM;
#pragma unroll
    for (int k = 0; k < EDIM; k++) {
        float w = eav[k];
        __half2 h = *reinterpret_cast<const __half2*>(Prow + k * C_OUT + c2);
        float2 p = __half22float2(h);
        acc.x = fmaf(w, p.x, acc.x);
        acc.y = fmaf(w, p.y, acc.y);
    }
    float* dst = &g_agg2[(size_t)d * C_OUT + c2];
    atomicAdd(dst + 0, acc.x);
    atomicAdd(dst + 1, acc.y);
}

// ---------------- final ------------------------------------------------------
__global__ void final_kernel(const float* __restrict__ root2,
                             const float* __restrict__ bias2,
                             float* __restrict__ out) {
    int n = blockIdx.x * blockDim.x + threadIdx.x;
    if (n >= N_CNT) return;
    float z[C_OUT];
#pragma unroll
    for (int c = 0; c < C_OUT; c++) z[c] = g_agg2[(size_t)n * C_OUT + c] + bias2[c];
    const float* hrow = g_h2 + (size_t)n * H2;
    for (int i = 0; i < H2; i++) {
        float hv = hrow[i];
#pragma unroll
        for (int c = 0; c < C_OUT; c++)
            z[c] = fmaf(hv, root2[i * C_OUT + c], z[c]);
    }
    float m = z[0];
#pragma unroll
    for (int c = 1; c < C_OUT; c++) m = fmaxf(m, z[c]);
    float sum = 0.f;
#pragma unroll
    for (int c = 0; c < C_OUT; c++) sum += expf(z[c] - m);
    float lse = m + logf(sum);
#pragma unroll
    for (int c = 0; c < C_OUT; c++) out[(size_t)n * C_OUT + c] = z[c] - lse;
}

// ---------------- launch -----------------------------------------------------
extern "C" void kernel_launch(void* const* d_in, const int* in_sizes, int n_in,
                              void* d_out, int out_size) {
    const float* x     = (const float*)d_in[0];
    const float* ea    = (const float*)d_in[1];
    const void*  eidx  = d_in[2];
    const float* W1    = (const float*)d_in[3];
    const float* b1    = (const float*)d_in[4];
    const float* We1   = (const float*)d_in[5];
    const float* be1   = (const float*)d_in[6];
    const float* root1 = (const float*)d_in[7];
    const float* bias1 = (const float*)d_in[8];
    const float* We2   = (const float*)d_in[9];
    const float* be2   = (const float*)d_in[10];
    const float* root2 = (const float*)d_in[11];
    const float* bias2 = (const float*)d_in[12];
    float* out = (float*)d_out;

    void* p_agg1 = nullptr; void* p_agg2 = nullptr;
    cudaGetSymbolAddress(&p_agg1, g_agg1);
    cudaGetSymbolAddress(&p_agg2, g_agg2);

    cudaFuncSetAttribute(mma_gemm_p1, cudaFuncAttributeMaxDynamicSharedMemorySize,
                         MMA_SMEM);
    cudaFuncSetAttribute(gemm_h, cudaFuncAttributeMaxDynamicSharedMemorySize,
                         GH_SMEM);
    cudaFuncSetAttribute(gemm_h2, cudaFuncAttributeMaxDynamicSharedMemorySize,
                         GH2_SMEM);
    cudaFuncSetAttribute(gemm_p2, cudaFuncAttributeMaxDynamicSharedMemorySize,
                         GP2_SMEM);

    dim3 blk(256);
    cudaMemsetAsync(p_agg1, 0, (size_t)N_CNT * H2 * sizeof(float));
    cudaMemsetAsync(p_agg2, 0, (size_t)N_CNT * C_OUT * sizeof(float));
    prep_all<<<(PR_TOT + 255) / 256, 256>>>(eidx, We1, be1, We2, be2);
    gemm_h<<<MPAD / 64, blk, GH_SMEM>>>(x, W1, b1);
    {
        dim3 grid(NPAD / 128, MPAD / 128);
        mma_gemm_p1<<<grid, blk, MMA_SMEM>>>();
    }
    edge_pass1<<<(E_CNT + 31) / 32, 256>>>(ea);
    gemm_h2<<<(N_CNT + 63) / 64, blk, GH2_SMEM>>>(root1, bias1);
    gemm_p2<<<(N_CNT + 63) / 64, blk, GP2_SMEM>>>();
    edge_pass2<<<(E_CNT * 5 + 255) / 256, 256>>>(ea);
    final_kernel<<<(N_CNT + 255) / 256, 256>>>(root2, bias2, out);
}

// round 15
// speedup vs baseline: 1.6274x; 1.6274x over previous
#include <cuda_runtime.h>
#include <cuda_bf16.h>
#include <cuda_fp16.h>
#include <math.h>
#include <stdint.h>

#define N_CNT 10000
#define E_CNT 30000
#define D_IN 64
#define EDIM 16
#define H1 128
#define H2 64
#define C_OUT 10

#define NB1 1088
#define NB2 170

#define MPAD 10112  // 79*128
#define NPAD 1152   // 9*128
#define KSPLIT 128  // single fp16 term: Ah x Bh

// ---------------- scratch ----------------------------------------------------
__device__ int   g_src[E_CNT];
__device__ int   g_dst[E_CNT];
__device__ float g_B2[H2 * NB2];
__device__ float g_h [N_CNT * H1];
__device__ __half g_Ab[(size_t)MPAD * KSPLIT];
__device__ __half g_Bb[(size_t)NPAD * KSPLIT];
__device__ __half g_P1[(size_t)N_CNT * NB1];
__device__ float g_agg1[N_CNT * H2];
__device__ float g_h2 [N_CNT * H2];
__device__ __half g_P2[(size_t)N_CNT * NB2];  // fp16 P2
__device__ float g_agg2[N_CNT * C_OUT];

// ---------------- helpers ----------------------------------------------------
__device__ __forceinline__ uint32_t smem_u32(const void* p) {
    uint32_t a;
    asm("{ .reg .u64 t; cvta.to.shared.u64 t, %1; cvt.u32.u64 %0, t; }"
        : "=r"(a) : "l"(p));
    return a;
}
__device__ __forceinline__ void ldmat_x4(uint32_t& r0, uint32_t& r1,
                                         uint32_t& r2, uint32_t& r3, uint32_t a) {
    asm volatile("ldmatrix.sync.aligned.m8n8.x4.shared.b16 {%0,%1,%2,%3}, [%4];"
                 : "=r"(r0), "=r"(r1), "=r"(r2), "=r"(r3) : "r"(a));
}
__device__ __forceinline__ void mma_f16(float* c, const uint32_t* a,
                                        const uint32_t* b) {
    asm volatile(
        "mma.sync.aligned.m16n8k16.row.col.f32.f16.f16.f32 "
        "{%0,%1,%2,%3}, {%4,%5,%6,%7}, {%8,%9}, {%0,%1,%2,%3};"
        : "+f"(c[0]), "+f"(c[1]), "+f"(c[2]), "+f"(c[3])
        : "r"(a[0]), "r"(a[1]), "r"(a[2]), "r"(a[3]), "r"(b[0]), "r"(b[1]));
}
__device__ __forceinline__ void cp16(uint32_t dst, const void* src) {
    asm volatile("cp.async.cg.shared.global [%0], [%1], 16;"
                 :: "r"(dst), "l"(src));
}
#define CP_COMMIT() asm volatile("cp.async.commit_group;" ::: "memory")
#define CP_WAIT0()  asm volatile("cp.async.wait_group 0;" ::: "memory")

// ---------------- launch 0: fused prep ---------------------------------------
#define PR_O1 (E_CNT)
#define PR_O2 (PR_O1 + NPAD * H1)
#define PR_O3 (PR_O2 + H2 * NB2)
#define PR_O4 (PR_O3 + N_CNT * H2)
#define PR_TOT (PR_O4 + N_CNT * C_OUT)

__global__ void prep_all(const void* eidx,
                         const float* __restrict__ We1,
                         const float* __restrict__ be1,
                         const float* __restrict__ We2,
                         const float* __restrict__ be2) {
    int idx = blockIdx.x * blockDim.x + threadIdx.x;
    if (idx >= PR_TOT) return;
    if (idx < PR_O1) {
        const int* p = (const int*)eidx;
        bool is64 = true;
#pragma unroll
        for (int j = 0; j < 8; j++) is64 &= (p[2 * j + 1] == 0);
        if (is64) {
            const long long* q = (const long long*)eidx;
            g_src[idx] = (int)q[idx];
            g_dst[idx] = (int)q[E_CNT + idx];
        } else {
            g_src[idx] = p[idx];
            g_dst[idx] = p[E_CNT + idx];
        }
    } else if (idx < PR_O2) {
        int t = idx - PR_O1;
        int n = t / H1, k = t - n * H1;
        float v = 0.f;
        if (n < EDIM * H2) {
            int ke = n >> 6, o = n & 63;
            v = We1[(size_t)ke * (H1 * H2) + k * H2 + o];
        } else if (n < NB1) {
            v = be1[(size_t)k * H2 + (n - EDIM * H2)];
        }
        g_Bb[(size_t)n * KSPLIT + k] = __float2half_rn(v);
    } else if (idx < PR_O3) {
        int t = idx - PR_O2;
        int i = t / NB2, col = t - i * NB2;
        float v;
        if (col < EDIM * C_OUT) {
            int k = col / C_OUT, c = col - k * C_OUT;
            v = We2[(size_t)k * (H2 * C_OUT) + i * C_OUT + c];
        } else {
            v = be2[(size_t)i * C_OUT + (col - EDIM * C_OUT)];
        }
        g_B2[t] = v;
    } else if (idx < PR_O4) {
        g_agg1[idx - PR_O3] = 0.f;
    } else {
        g_agg2[idx - PR_O4] = 0.f;
    }
}

// ---------------- launch 1: gemm_h: h=relu(x@W1+b1) + fp16 epilogue ----------
#define HPAD_W 132
#define HPAD_A 68
#define GH_SMEM ((64 * HPAD_W + 64 * HPAD_A) * 4)

__global__ __launch_bounds__(256, 2)
void gemm_h(const float* __restrict__ x, const float* __restrict__ W1,
            const float* __restrict__ b1) {
    extern __shared__ float fsm[];
    float* Ws = fsm;
    float* As = fsm + 64 * HPAD_W;
    int tid = threadIdx.x;
    int tx = tid & 31, ty = tid >> 5;
    int m0 = blockIdx.x * 64;

    for (int i = tid; i < 2048; i += 256) {
        int k = i >> 5, n4 = (i & 31) * 4;
        float4 v = *reinterpret_cast<const float4*>(&W1[k * H1 + n4]);
        *reinterpret_cast<float4*>(&Ws[k * HPAD_W + n4]) = v;
    }
    for (int i = tid; i < 1024; i += 256) {
        int m = i >> 4, k4 = (i & 15) * 4;
        float4 v = (m0 + m < N_CNT)
            ? *reinterpret_cast<const float4*>(&x[(size_t)(m0 + m) * D_IN + k4])
            : make_float4(0.f, 0.f, 0.f, 0.f);
        As[(k4 + 0) * HPAD_A + m] = v.x;
        As[(k4 + 1) * HPAD_A + m] = v.y;
        As[(k4 + 2) * HPAD_A + m] = v.z;
        As[(k4 + 3) * HPAD_A + m] = v.w;
    }
    __syncthreads();

    float acc[8][4];
#pragma unroll
    for (int r = 0; r < 8; r++)
#pragma unroll
        for (int s = 0; s < 4; s++) acc[r][s] = 0.f;

#pragma unroll 4
    for (int k = 0; k < 64; k++) {
        float4 a0 = *reinterpret_cast<const float4*>(&As[k * HPAD_A + ty * 8]);
        float4 a1 = *reinterpret_cast<const float4*>(&As[k * HPAD_A + ty * 8 + 4]);
        float4 w  = *reinterpret_cast<const float4*>(&Ws[k * HPAD_W + tx * 4]);
        float a[8] = {a0.x, a0.y, a0.z, a0.w, a1.x, a1.y, a1.z, a1.w};
        float ww[4] = {w.x, w.y, w.z, w.w};
#pragma unroll
        for (int r = 0; r < 8; r++)
#pragma unroll
            for (int s = 0; s < 4; s++)
                acc[r][s] = fmaf(a[r], ww[s], acc[r][s]);
    }

    float bv[4];
#pragma unroll
    for (int s = 0; s < 4; s++) bv[s] = b1[tx * 4 + s];

#pragma unroll
    for (int r = 0; r < 8; r++) {
        int m = m0 + ty * 8 + r;
        float v[4];
#pragma unroll
        for (int s = 0; s < 4; s++) v[s] = fmaxf(acc[r][s] + bv[s], 0.f);
        if (m < N_CNT)
            *reinterpret_cast<float4*>(&g_h[(size_t)m * H1 + tx * 4]) =
                make_float4(v[0], v[1], v[2], v[3]);
        __half ah[4];
#pragma unroll
        for (int s = 0; s < 4; s++) ah[s] = __float2half_rn(v[s]);
        uint32_t hi0 = ((uint32_t)__half_as_ushort(ah[1]) << 16) |
                       __half_as_ushort(ah[0]);
        uint32_t hi1 = ((uint32_t)__half_as_ushort(ah[3]) << 16) |
                       __half_as_ushort(ah[2]);
        *reinterpret_cast<uint2*>(&g_Ab[(size_t)m * KSPLIT + tx * 4]) =
            make_uint2(hi0, hi1);
    }
}

// ---------------- launch 2: mma fp16 GEMM, K=128 single stage ----------------
#define SSTR 136
#define MMA_SMEM (2 * 128 * SSTR * 2)   // A + B, 69632 B

__global__ __launch_bounds__(256, 2)
void mma_gemm_p1() {
    extern __shared__ __half sm[];
    __half* As = sm;
    __half* Bs = sm + 128 * SSTR;

    int tid = threadIdx.x;
    int wid = tid >> 5, lane = tid & 31;
    int row0 = blockIdx.y * 128;
    int col0 = blockIdx.x * 128;
    int wm0 = (wid >> 2) * 64;
    int wn0 = (wid & 3) * 32;

    int lrow = tid >> 1;
    int lq   = (tid & 1) * 8;
    const char* Ag = (const char*)(g_Ab) + (size_t)(row0 + lrow) * (KSPLIT * 2);
    const char* Bg = (const char*)(g_Bb) + (size_t)(col0 + lrow) * (KSPLIT * 2);
    uint32_t As_base = smem_u32(As);
    uint32_t Bs_base = smem_u32(Bs);
    uint32_t a_st = As_base + (uint32_t)(lrow * SSTR + lq * 8) * 2;
    uint32_t b_st = Bs_base + (uint32_t)(lrow * SSTR + lq * 8) * 2;

#pragma unroll
    for (int t = 0; t < 8; t++) {
        cp16(a_st + t * 16, Ag + (lq + t) * 16);
        cp16(b_st + t * 16, Bg + (lq + t) * 16);
    }
    CP_COMMIT();

    float acc[4][4][4];
#pragma unroll
    for (int i = 0; i < 4; i++)
#pragma unroll
        for (int j = 0; j < 4; j++)
#pragma unroll
            for (int q = 0; q < 4; q++) acc[i][j][q] = 0.f;

    int a_r = wm0 + (lane & 7) + ((lane >> 3) & 1) * 8;
    int a_c = ((lane >> 4) & 1) * 8;
    int b_r = wn0 + (lane & 7) + ((lane >> 4) & 1) * 8;
    int b_c = ((lane >> 3) & 1) * 8;

    CP_WAIT0();
    __syncthreads();

#pragma unroll
    for (int ks = 0; ks < 8; ks++) {
        int k0 = ks * 16;
        uint32_t afr[4][4], bfr[4][2];
#pragma unroll
        for (int i = 0; i < 4; i++) {
            uint32_t addr = As_base + (uint32_t)((a_r + i * 16) * SSTR + k0 + a_c) * 2;
            ldmat_x4(afr[i][0], afr[i][1], afr[i][2], afr[i][3], addr);
        }
#pragma unroll
        for (int jp = 0; jp < 2; jp++) {
            uint32_t addr = Bs_base + (uint32_t)((b_r + jp * 16) * SSTR + k0 + b_c) * 2;
            ldmat_x4(bfr[jp * 2][0], bfr[jp * 2][1],
                     bfr[jp * 2 + 1][0], bfr[jp * 2 + 1][1], addr);
        }
#pragma unroll
        for (int i = 0; i < 4; i++)
#pragma unroll
            for (int j = 0; j < 4; j++)
                mma_f16(acc[i][j], afr[i], bfr[j]);
    }

    int erow = lane >> 2;
    int ecol = (lane & 3) * 2;
#pragma unroll
    for (int i = 0; i < 4; i++) {
        int mg0 = row0 + wm0 + i * 16 + erow;
#pragma unroll
        for (int j = 0; j < 4; j++) {
            int ng = col0 + wn0 + j * 8 + ecol;
            if (ng >= NB1) continue;
            if (mg0 < N_CNT)
                *reinterpret_cast<__half2*>(&g_P1[(size_t)mg0 * NB1 + ng]) =
                    __floats2half2_rn(acc[i][j][0], acc[i][j][1]);
            if (mg0 + 8 < N_CNT)
                *reinterpret_cast<__half2*>(&g_P1[(size_t)(mg0 + 8) * NB1 + ng]) =
                    __floats2half2_rn(acc[i][j][2], acc[i][j][3]);
        }
    }
}

// ---------------- launch 3: edge pass 1 (fp16 gather, 16 thr/edge) -----------
__global__ void edge_pass1(const float* __restrict__ ea) {
    int le = threadIdx.x >> 4;
    int tq = threadIdx.x & 15;
    int e  = blockIdx.x * 16 + le;
    __shared__ float sea[16][17];
    if (e < E_CNT) sea[le][tq] = ea[(size_t)e * EDIM + tq];
    __syncthreads();
    if (e >= E_CNT) return;
    int s = g_src[e], d = g_dst[e];
    const __half* Prow = g_P1 + (size_t)s * NB1 + tq * 4;
    float4 acc;
    {
        uint2 raw = *reinterpret_cast<const uint2*>(Prow + EDIM * H2);
        __half2 h0 = *reinterpret_cast<__half2*>(&raw.x);
        __half2 h1 = *reinterpret_cast<__half2*>(&raw.y);
        float2 f0 = __half22float2(h0), f1 = __half22float2(h1);
        acc = make_float4(f0.x, f0.y, f1.x, f1.y);
    }
#pragma unroll
    for (int k = 0; k < EDIM; k++) {
        float w = sea[le][k];
        uint2 raw = *reinterpret_cast<const uint2*>(Prow + k * H2);
        __half2 h0 = *reinterpret_cast<__half2*>(&raw.x);
        __half2 h1 = *reinterpret_cast<__half2*>(&raw.y);
        float2 f0 = __half22float2(h0), f1 = __half22float2(h1);
        acc.x = fmaf(w, f0.x, acc.x);
        acc.y = fmaf(w, f0.y, acc.y);
        acc.z = fmaf(w, f1.x, acc.z);
        acc.w = fmaf(w, f1.y, acc.w);
    }
    float* dst = &g_agg1[(size_t)d * H2 + tq * 4];
    atomicAdd(dst + 0, acc.x);
    atomicAdd(dst + 1, acc.y);
    atomicAdd(dst + 2, acc.z);
    atomicAdd(dst + 3, acc.w);
}

// ---------------- launch 4: gemm_h2 ------------------------------------------
#define GH2_RS 68
#define GH2_AS 68
#define GH2_SMEM ((128 * GH2_RS + 128 * GH2_AS) * 4)

__global__ __launch_bounds__(256, 2)
void gemm_h2(const float* __restrict__ root1, const float* __restrict__ bias1) {
    extern __shared__ float s2[];
    float* rs = s2;
    float* as = s2 + 128 * GH2_RS;
    int tid = threadIdx.x;
    int tx = tid & 15, ty = tid >> 4;
    int m0 = blockIdx.x * 64;

    for (int i = tid; i < 2048; i += 256) {
        int k = i >> 4, n4 = (i & 15) * 4;
        *reinterpret_cast<float4*>(&rs[k * GH2_RS + n4]) =
            *reinterpret_cast<const float4*>(&root1[k * H2 + n4]);
    }
    for (int i = tid; i < 2048; i += 256) {
        int m = i >> 5, k4 = (i & 31) * 4;
        float4 v = (m0 + m < N_CNT)
            ? *reinterpret_cast<const float4*>(&g_h[(size_t)(m0 + m) * H1 + k4])
            : make_float4(0.f, 0.f, 0.f, 0.f);
        as[(k4 + 0) * GH2_AS + m] = v.x;
        as[(k4 + 1) * GH2_AS + m] = v.y;
        as[(k4 + 2) * GH2_AS + m] = v.z;
        as[(k4 + 3) * GH2_AS + m] = v.w;
    }
    __syncthreads();

    float acc[4][4];
#pragma unroll
    for (int r = 0; r < 4; r++)
#pragma unroll
        for (int s = 0; s < 4; s++) acc[r][s] = 0.f;
#pragma unroll 4
    for (int k = 0; k < 128; k++) {
        float4 a4 = *reinterpret_cast<const float4*>(&as[k * GH2_AS + ty * 4]);
        float4 w4 = *reinterpret_cast<const float4*>(&rs[k * GH2_RS + tx * 4]);
        float a[4] = {a4.x, a4.y, a4.z, a4.w};
        float w[4] = {w4.x, w4.y, w4.z, w4.w};
#pragma unroll
        for (int r = 0; r < 4; r++)
#pragma unroll
            for (int s = 0; s < 4; s++)
                acc[r][s] = fmaf(a[r], w[s], acc[r][s]);
    }
    float bv[4];
#pragma unroll
    for (int s = 0; s < 4; s++) bv[s] = bias1[tx * 4 + s];
#pragma unroll
    for (int r = 0; r < 4; r++) {
        int m = m0 + ty * 4 + r;
        if (m >= N_CNT) continue;
        float4 ag = *reinterpret_cast<const float4*>(&g_agg1[(size_t)m * H2 + tx * 4]);
        float v0 = fmaxf(acc[r][0] + bv[0] + ag.x, 0.f);
        float v1 = fmaxf(acc[r][1] + bv[1] + ag.y, 0.f);
        float v2 = fmaxf(acc[r][2] + bv[2] + ag.z, 0.f);
        float v3 = fmaxf(acc[r][3] + bv[3] + ag.w, 0.f);
        *reinterpret_cast<float4*>(&g_h2[(size_t)m * H2 + tx * 4]) =
            make_float4(v0, v1, v2, v3);
    }
}

// ---------------- launch 5: gemm_p2 (fp16 out) -------------------------------
#define GP2_HS 68
#define GP2_BS 172
#define GP2_SMEM ((64 * GP2_HS + 64 * GP2_BS) * 4)

__global__ __launch_bounds__(256, 2)
void gemm_p2() {
    extern __shared__ float s3[];
    float* h2t = s3;
    float* b2s = s3 + 64 * GP2_HS;
    int tid = threadIdx.x;
    int tx = tid & 15, ty = tid >> 4;
    int m0 = blockIdx.x * 64;

    for (int i = tid; i < 1024; i += 256) {
        int m = i >> 4, k4 = (i & 15) * 4;
        float4 v = (m0 + m < N_CNT)
            ? *reinterpret_cast<const float4*>(&g_h2[(size_t)(m0 + m) * H2 + k4])
            : make_float4(0.f, 0.f, 0.f, 0.f);
        h2t[(k4 + 0) * GP2_HS + m] = v.x;
        h2t[(k4 + 1) * GP2_HS + m] = v.y;
        h2t[(k4 + 2) * GP2_HS + m] = v.z;
        h2t[(k4 + 3) * GP2_HS + m] = v.w;
    }
    for (int i = tid; i < H2 * NB2; i += 256) {
        int k = i / NB2, c = i - k * NB2;
        b2s[k * GP2_BS + c] = g_B2[i];
    }
    __syncthreads();

#pragma unroll
    for (int p = 0; p < 3; p++) {
        int c0 = p * 64 + tx * 4;
        if (c0 >= NB2) break;
        float acc[4][4];
#pragma unroll
        for (int r = 0; r < 4; r++)
#pragma unroll
            for (int s = 0; s < 4; s++) acc[r][s] = 0.f;
#pragma unroll 4
        for (int k = 0; k < 64; k++) {
            float4 a4 = *reinterpret_cast<const float4*>(&h2t[k * GP2_HS + ty * 4]);
            float4 b4 = *reinterpret_cast<const float4*>(&b2s[k * GP2_BS + c0]);
            float a[4] = {a4.x, a4.y, a4.z, a4.w};
            float b[4] = {b4.x, b4.y, b4.z, b4.w};
#pragma unroll
            for (int r = 0; r < 4; r++)
#pragma unroll
                for (int s = 0; s < 4; s++)
                    acc[r][s] = fmaf(a[r], b[s], acc[r][s]);
        }
#pragma unroll
        for (int r = 0; r < 4; r++) {
            int m = m0 + ty * 4 + r;
            if (m >= N_CNT) continue;
            __half* dst = &g_P2[(size_t)m * NB2 + c0];
            if (c0 + 3 < NB2) {
                *reinterpret_cast<__half2*>(dst) =
                    __floats2half2_rn(acc[r][0], acc[r][1]);
                *reinterpret_cast<__half2*>(dst + 2) =
                    __floats2half2_rn(acc[r][2], acc[r][3]);
            } else {
#pragma unroll
                for (int s = 0; s < 4; s++)
                    if (c0 + s < NB2) dst[s] = __float2half_rn(acc[r][s]);
            }
        }
    }
}

// ---------------- launch 6: edge pass 2 (fp16, half2, 5 thr/edge) ------------
__global__ void edge_pass2(const float* __restrict__ ea) {
    int t = blockIdx.x * blockDim.x + threadIdx.x;
    if (t >= E_CNT * 5) return;
    int e = t / 5, c2 = (t - (t / 5) * 5) * 2;
    int s = g_src[e], d = g_dst[e];
    const __half* Prow = g_P2 + (size_t)s * NB2;
    float2 acc;
    {
        __half2 h = *reinterpret_cast<const __half2*>(Prow + EDIM * C_OUT + c2);
        acc = __half22float2(h);
    }
    const float* eav = ea + (size_t)e * EDIM;
#pragma unroll
    for (int k = 0; k < EDIM; k++) {
        float w = eav[k];
        __half2 h = *reinterpret_cast<const __half2*>(Prow + k * C_OUT + c2);
        float2 p = __half22float2(h);
        acc.x = fmaf(w, p.x, acc.x);
        acc.y = fmaf(w, p.y, acc.y);
    }
    float* dst = &g_agg2[(size_t)d * C_OUT + c2];
    atomicAdd(dst + 0, acc.x);
    atomicAdd(dst + 1, acc.y);
}

// ---------------- launch 7: final --------------------------------------------
__global__ void final_kernel(const float* __restrict__ root2,
                             const float* __restrict__ bias2,
                             float* __restrict__ out) {
    int n = blockIdx.x * blockDim.x + threadIdx.x;
    if (n >= N_CNT) return;
    float z[C_OUT];
#pragma unroll
    for (int c = 0; c < C_OUT; c++) z[c] = g_agg2[(size_t)n * C_OUT + c] + bias2[c];
    const float* hrow = g_h2 + (size_t)n * H2;
    for (int i = 0; i < H2; i++) {
        float hv = hrow[i];
#pragma unroll
        for (int c = 0; c < C_OUT; c++)
            z[c] = fmaf(hv, root2[i * C_OUT + c], z[c]);
    }
    float m = z[0];
#pragma unroll
    for (int c = 1; c < C_OUT; c++) m = fmaxf(m, z[c]);
    float sum = 0.f;
#pragma unroll
    for (int c = 0; c < C_OUT; c++) sum += expf(z[c] - m);
    float lse = m + logf(sum);
#pragma unroll
    for (int c = 0; c < C_OUT; c++) out[(size_t)n * C_OUT + c] = z[c] - lse;
}

// ---------------- launch -----------------------------------------------------
extern "C" void kernel_launch(void* const* d_in, const int* in_sizes, int n_in,
                              void* d_out, int out_size) {
    const float* x     = (const float*)d_in[0];
    const float* ea    = (const float*)d_in[1];
    const void*  eidx  = d_in[2];
    const float* W1    = (const float*)d_in[3];
    const float* b1    = (const float*)d_in[4];
    const float* We1   = (const float*)d_in[5];
    const float* be1   = (const float*)d_in[6];
    const float* root1 = (const float*)d_in[7];
    const float* bias1 = (const float*)d_in[8];
    const float* We2   = (const float*)d_in[9];
    const float* be2   = (const float*)d_in[10];
    const float* root2 = (const float*)d_in[11];
    const float* bias2 = (const float*)d_in[12];
    float* out = (float*)d_out;

    cudaFuncSetAttribute(mma_gemm_p1, cudaFuncAttributeMaxDynamicSharedMemorySize,
                         MMA_SMEM);
    cudaFuncSetAttribute(gemm_h, cudaFuncAttributeMaxDynamicSharedMemorySize,
                         GH_SMEM);
    cudaFuncSetAttribute(gemm_h2, cudaFuncAttributeMaxDynamicSharedMemorySize,
                         GH2_SMEM);
    cudaFuncSetAttribute(gemm_p2, cudaFuncAttributeMaxDynamicSharedMemorySize,
                         GP2_SMEM);

    dim3 blk(256);
    prep_all<<<(PR_TOT + 255) / 256, 256>>>(eidx, We1, be1, We2, be2);
    gemm_h<<<MPAD / 64, blk, GH_SMEM>>>(x, W1, b1);
    {
        dim3 grid(NPAD / 128, MPAD / 128);
        mma_gemm_p1<<<grid, blk, MMA_SMEM>>>();
    }
    edge_pass1<<<(E_CNT + 15) / 16, 256>>>(ea);
    gemm_h2<<<(N_CNT + 63) / 64, blk, GH2_SMEM>>>(root1, bias1);
    gemm_p2<<<(N_CNT + 63) / 64, blk, GP2_SMEM>>>();
    edge_pass2<<<(E_CNT * 5 + 255) / 256, 256>>>(ea);
    final_kernel<<<(N_CNT + 255) / 256, 256>>>(root2, bias2, out);
}

// round 16
// speedup vs baseline: 1.6609x; 1.0206x over previous
#include <cuda_runtime.h>
#include <cuda_bf16.h>
#include <cuda_fp16.h>
#include <math.h>
#include <stdint.h>

#define N_CNT 10000
#define E_CNT 30000
#define D_IN 64
#define EDIM 16
#define H1 128
#define H2 64
#define C_OUT 10

#define NB1 1088
#define NB2 170

#define MPAD 10112  // 79*128
#define NPAD 1152   // 9*128
#define KSPLIT 128  // single fp16 term: Ah x Bh

// ---------------- scratch ----------------------------------------------------
__device__ int   g_src[E_CNT];
__device__ int   g_dst[E_CNT];
__device__ float g_B2[H2 * NB2];
__device__ float g_h [N_CNT * H1];
__device__ __half g_Ab[(size_t)MPAD * KSPLIT];
__device__ __half g_Bb[(size_t)NPAD * KSPLIT];
__device__ __half g_P1[(size_t)N_CNT * NB1];
__device__ float g_agg1[N_CNT * H2];
__device__ float g_h2 [N_CNT * H2];
__device__ __half g_P2[(size_t)N_CNT * NB2];
__device__ float g_agg2[N_CNT * C_OUT];

// ---------------- helpers ----------------------------------------------------
__device__ __forceinline__ uint32_t smem_u32(const void* p) {
    uint32_t a;
    asm("{ .reg .u64 t; cvta.to.shared.u64 t, %1; cvt.u32.u64 %0, t; }"
        : "=r"(a) : "l"(p));
    return a;
}
__device__ __forceinline__ void ldmat_x4(uint32_t& r0, uint32_t& r1,
                                         uint32_t& r2, uint32_t& r3, uint32_t a) {
    asm volatile("ldmatrix.sync.aligned.m8n8.x4.shared.b16 {%0,%1,%2,%3}, [%4];"
                 : "=r"(r0), "=r"(r1), "=r"(r2), "=r"(r3) : "r"(a));
}
__device__ __forceinline__ void mma_f16(float* c, const uint32_t* a,
                                        const uint32_t* b) {
    asm volatile(
        "mma.sync.aligned.m16n8k16.row.col.f32.f16.f16.f32 "
        "{%0,%1,%2,%3}, {%4,%5,%6,%7}, {%8,%9}, {%0,%1,%2,%3};"
        : "+f"(c[0]), "+f"(c[1]), "+f"(c[2]), "+f"(c[3])
        : "r"(a[0]), "r"(a[1]), "r"(a[2]), "r"(a[3]), "r"(b[0]), "r"(b[1]));
}
__device__ __forceinline__ void cp16(uint32_t dst, const void* src) {
    asm volatile("cp.async.cg.shared.global [%0], [%1], 16;"
                 :: "r"(dst), "l"(src));
}
#define CP_COMMIT() asm volatile("cp.async.commit_group;" ::: "memory")
#define CP_WAIT0()  asm volatile("cp.async.wait_group 0;" ::: "memory")

// ---------------- launch 0: fused front = gemm_h blocks + prep blocks --------
// blocks [0, GH_BLOCKS): h = relu(x@W1+b1) + fp16 A' epilogue
// blocks [GH_BLOCKS, ...): prep (idx convert, B1' build, B2 build, agg zero)
#define GH_BLOCKS (MPAD / 64)           // 158
#define PR_O1 (E_CNT)
#define PR_O2 (PR_O1 + NPAD * H1)
#define PR_O3 (PR_O2 + H2 * NB2)
#define PR_O4 (PR_O3 + N_CNT * H2)
#define PR_TOT (PR_O4 + N_CNT * C_OUT)
#define PR_BLOCKS ((PR_TOT + 255) / 256)

#define HPAD_W 132
#define HPAD_A 68
#define GH_SMEM ((64 * HPAD_W + 64 * HPAD_A) * 4)

__global__ __launch_bounds__(256, 2)
void fused_front(const float* __restrict__ x, const float* __restrict__ W1,
                 const float* __restrict__ b1, const void* eidx,
                 const float* __restrict__ We1, const float* __restrict__ be1,
                 const float* __restrict__ We2, const float* __restrict__ be2) {
    if (blockIdx.x >= GH_BLOCKS) {
        // ---- prep path ----
        int idx = (blockIdx.x - GH_BLOCKS) * blockDim.x + threadIdx.x;
        if (idx >= PR_TOT) return;
        if (idx < PR_O1) {
            const int* p = (const int*)eidx;
            bool is64 = true;
#pragma unroll
            for (int j = 0; j < 8; j++) is64 &= (p[2 * j + 1] == 0);
            if (is64) {
                const long long* q = (const long long*)eidx;
                g_src[idx] = (int)q[idx];
                g_dst[idx] = (int)q[E_CNT + idx];
            } else {
                g_src[idx] = p[idx];
                g_dst[idx] = p[E_CNT + idx];
            }
        } else if (idx < PR_O2) {
            int t = idx - PR_O1;
            int n = t / H1, k = t - n * H1;
            float v = 0.f;
            if (n < EDIM * H2) {
                int ke = n >> 6, o = n & 63;
                v = We1[(size_t)ke * (H1 * H2) + k * H2 + o];
            } else if (n < NB1) {
                v = be1[(size_t)k * H2 + (n - EDIM * H2)];
            }
            g_Bb[(size_t)n * KSPLIT + k] = __float2half_rn(v);
        } else if (idx < PR_O3) {
            int t = idx - PR_O2;
            int i = t / NB2, col = t - i * NB2;
            float v;
            if (col < EDIM * C_OUT) {
                int k = col / C_OUT, c = col - k * C_OUT;
                v = We2[(size_t)k * (H2 * C_OUT) + i * C_OUT + c];
            } else {
                v = be2[(size_t)i * C_OUT + (col - EDIM * C_OUT)];
            }
            g_B2[t] = v;
        } else if (idx < PR_O4) {
            g_agg1[idx - PR_O3] = 0.f;
        } else {
            g_agg2[idx - PR_O4] = 0.f;
        }
        return;
    }

    // ---- gemm_h path ----
    extern __shared__ float fsm[];
    float* Ws = fsm;
    float* As = fsm + 64 * HPAD_W;
    int tid = threadIdx.x;
    int tx = tid & 31, ty = tid >> 5;
    int m0 = blockIdx.x * 64;

    for (int i = tid; i < 2048; i += 256) {
        int k = i >> 5, n4 = (i & 31) * 4;
        float4 v = *reinterpret_cast<const float4*>(&W1[k * H1 + n4]);
        *reinterpret_cast<float4*>(&Ws[k * HPAD_W + n4]) = v;
    }
    for (int i = tid; i < 1024; i += 256) {
        int m = i >> 4, k4 = (i & 15) * 4;
        float4 v = (m0 + m < N_CNT)
            ? *reinterpret_cast<const float4*>(&x[(size_t)(m0 + m) * D_IN + k4])
            : make_float4(0.f, 0.f, 0.f, 0.f);
        As[(k4 + 0) * HPAD_A + m] = v.x;
        As[(k4 + 1) * HPAD_A + m] = v.y;
        As[(k4 + 2) * HPAD_A + m] = v.z;
        As[(k4 + 3) * HPAD_A + m] = v.w;
    }
    __syncthreads();

    float acc[8][4];
#pragma unroll
    for (int r = 0; r < 8; r++)
#pragma unroll
        for (int s = 0; s < 4; s++) acc[r][s] = 0.f;

#pragma unroll 4
    for (int k = 0; k < 64; k++) {
        float4 a0 = *reinterpret_cast<const float4*>(&As[k * HPAD_A + ty * 8]);
        float4 a1 = *reinterpret_cast<const float4*>(&As[k * HPAD_A + ty * 8 + 4]);
        float4 w  = *reinterpret_cast<const float4*>(&Ws[k * HPAD_W + tx * 4]);
        float a[8] = {a0.x, a0.y, a0.z, a0.w, a1.x, a1.y, a1.z, a1.w};
        float ww[4] = {w.x, w.y, w.z, w.w};
#pragma unroll
        for (int r = 0; r < 8; r++)
#pragma unroll
            for (int s = 0; s < 4; s++)
                acc[r][s] = fmaf(a[r], ww[s], acc[r][s]);
    }

    float bv[4];
#pragma unroll
    for (int s = 0; s < 4; s++) bv[s] = b1[tx * 4 + s];

#pragma unroll
    for (int r = 0; r < 8; r++) {
        int m = m0 + ty * 8 + r;
        float v[4];
#pragma unroll
        for (int s = 0; s < 4; s++) v[s] = fmaxf(acc[r][s] + bv[s], 0.f);
        if (m < N_CNT)
            *reinterpret_cast<float4*>(&g_h[(size_t)m * H1 + tx * 4]) =
                make_float4(v[0], v[1], v[2], v[3]);
        __half ah[4];
#pragma unroll
        for (int s = 0; s < 4; s++) ah[s] = __float2half_rn(v[s]);
        uint32_t hi0 = ((uint32_t)__half_as_ushort(ah[1]) << 16) |
                       __half_as_ushort(ah[0]);
        uint32_t hi1 = ((uint32_t)__half_as_ushort(ah[3]) << 16) |
                       __half_as_ushort(ah[2]);
        *reinterpret_cast<uint2*>(&g_Ab[(size_t)m * KSPLIT + tx * 4]) =
            make_uint2(hi0, hi1);
    }
}

// ---------------- launch 1: mma fp16 GEMM, K=128 single stage ----------------
#define SSTR 136
#define MMA_SMEM (2 * 128 * SSTR * 2)   // A + B, 69632 B

__global__ __launch_bounds__(256, 2)
void mma_gemm_p1() {
    extern __shared__ __half sm[];
    __half* As = sm;
    __half* Bs = sm + 128 * SSTR;

    int tid = threadIdx.x;
    int wid = tid >> 5, lane = tid & 31;
    int row0 = blockIdx.y * 128;
    int col0 = blockIdx.x * 128;
    int wm0 = (wid >> 2) * 64;
    int wn0 = (wid & 3) * 32;

    int lrow = tid >> 1;
    int lq   = (tid & 1) * 8;
    const char* Ag = (const char*)(g_Ab) + (size_t)(row0 + lrow) * (KSPLIT * 2);
    const char* Bg = (const char*)(g_Bb) + (size_t)(col0 + lrow) * (KSPLIT * 2);
    uint32_t As_base = smem_u32(As);
    uint32_t Bs_base = smem_u32(Bs);
    uint32_t a_st = As_base + (uint32_t)(lrow * SSTR + lq * 8) * 2;
    uint32_t b_st = Bs_base + (uint32_t)(lrow * SSTR + lq * 8) * 2;

#pragma unroll
    for (int t = 0; t < 8; t++) {
        cp16(a_st + t * 16, Ag + (lq + t) * 16);
        cp16(b_st + t * 16, Bg + (lq + t) * 16);
    }
    CP_COMMIT();

    float acc[4][4][4];
#pragma unroll
    for (int i = 0; i < 4; i++)
#pragma unroll
        for (int j = 0; j < 4; j++)
#pragma unroll
            for (int q = 0; q < 4; q++) acc[i][j][q] = 0.f;

    int a_r = wm0 + (lane & 7) + ((lane >> 3) & 1) * 8;
    int a_c = ((lane >> 4) & 1) * 8;
    int b_r = wn0 + (lane & 7) + ((lane >> 4) & 1) * 8;
    int b_c = ((lane >> 3) & 1) * 8;

    CP_WAIT0();
    __syncthreads();

#pragma unroll
    for (int ks = 0; ks < 8; ks++) {
        int k0 = ks * 16;
        uint32_t afr[4][4], bfr[4][2];
#pragma unroll
        for (int i = 0; i < 4; i++) {
            uint32_t addr = As_base + (uint32_t)((a_r + i * 16) * SSTR + k0 + a_c) * 2;
            ldmat_x4(afr[i][0], afr[i][1], afr[i][2], afr[i][3], addr);
        }
#pragma unroll
        for (int jp = 0; jp < 2; jp++) {
            uint32_t addr = Bs_base + (uint32_t)((b_r + jp * 16) * SSTR + k0 + b_c) * 2;
            ldmat_x4(bfr[jp * 2][0], bfr[jp * 2][1],
                     bfr[jp * 2 + 1][0], bfr[jp * 2 + 1][1], addr);
        }
#pragma unroll
        for (int i = 0; i < 4; i++)
#pragma unroll
            for (int j = 0; j < 4; j++)
                mma_f16(acc[i][j], afr[i], bfr[j]);
    }

    int erow = lane >> 2;
    int ecol = (lane & 3) * 2;
#pragma unroll
    for (int i = 0; i < 4; i++) {
        int mg0 = row0 + wm0 + i * 16 + erow;
#pragma unroll
        for (int j = 0; j < 4; j++) {
            int ng = col0 + wn0 + j * 8 + ecol;
            if (ng >= NB1) continue;
            if (mg0 < N_CNT)
                *reinterpret_cast<__half2*>(&g_P1[(size_t)mg0 * NB1 + ng]) =
                    __floats2half2_rn(acc[i][j][0], acc[i][j][1]);
            if (mg0 + 8 < N_CNT)
                *reinterpret_cast<__half2*>(&g_P1[(size_t)(mg0 + 8) * NB1 + ng]) =
                    __floats2half2_rn(acc[i][j][2], acc[i][j][3]);
        }
    }
}

// ---------------- launch 2: edge pass 1 (fp16 gather, 16 thr/edge) -----------
__global__ void edge_pass1(const float* __restrict__ ea) {
    int le = threadIdx.x >> 4;
    int tq = threadIdx.x & 15;
    int e  = blockIdx.x * 16 + le;
    __shared__ float sea[16][17];
    if (e < E_CNT) sea[le][tq] = ea[(size_t)e * EDIM + tq];
    __syncthreads();
    if (e >= E_CNT) return;
    int s = g_src[e], d = g_dst[e];
    const __half* Prow = g_P1 + (size_t)s * NB1 + tq * 4;
    float4 acc;
    {
        uint2 raw = *reinterpret_cast<const uint2*>(Prow + EDIM * H2);
        __half2 h0 = *reinterpret_cast<__half2*>(&raw.x);
        __half2 h1 = *reinterpret_cast<__half2*>(&raw.y);
        float2 f0 = __half22float2(h0), f1 = __half22float2(h1);
        acc = make_float4(f0.x, f0.y, f1.x, f1.y);
    }
#pragma unroll
    for (int k = 0; k < EDIM; k++) {
        float w = sea[le][k];
        uint2 raw = *reinterpret_cast<const uint2*>(Prow + k * H2);
        __half2 h0 = *reinterpret_cast<__half2*>(&raw.x);
        __half2 h1 = *reinterpret_cast<__half2*>(&raw.y);
        float2 f0 = __half22float2(h0), f1 = __half22float2(h1);
        acc.x = fmaf(w, f0.x, acc.x);
        acc.y = fmaf(w, f0.y, acc.y);
        acc.z = fmaf(w, f1.x, acc.z);
        acc.w = fmaf(w, f1.y, acc.w);
    }
    float* dst = &g_agg1[(size_t)d * H2 + tq * 4];
    atomicAdd(dst + 0, acc.x);
    atomicAdd(dst + 1, acc.y);
    atomicAdd(dst + 2, acc.z);
    atomicAdd(dst + 3, acc.w);
}

// ---------------- launch 3: gemm_h2 ------------------------------------------
#define GH2_RS 68
#define GH2_AS 68
#define GH2_SMEM ((128 * GH2_RS + 128 * GH2_AS) * 4)

__global__ __launch_bounds__(256, 2)
void gemm_h2(const float* __restrict__ root1, const float* __restrict__ bias1) {
    extern __shared__ float s2[];
    float* rs = s2;
    float* as = s2 + 128 * GH2_RS;
    int tid = threadIdx.x;
    int tx = tid & 15, ty = tid >> 4;
    int m0 = blockIdx.x * 64;

    for (int i = tid; i < 2048; i += 256) {
        int k = i >> 4, n4 = (i & 15) * 4;
        *reinterpret_cast<float4*>(&rs[k * GH2_RS + n4]) =
            *reinterpret_cast<const float4*>(&root1[k * H2 + n4]);
    }
    for (int i = tid; i < 2048; i += 256) {
        int m = i >> 5, k4 = (i & 31) * 4;
        float4 v = (m0 + m < N_CNT)
            ? *reinterpret_cast<const float4*>(&g_h[(size_t)(m0 + m) * H1 + k4])
            : make_float4(0.f, 0.f, 0.f, 0.f);
        as[(k4 + 0) * GH2_AS + m] = v.x;
        as[(k4 + 1) * GH2_AS + m] = v.y;
        as[(k4 + 2) * GH2_AS + m] = v.z;
        as[(k4 + 3) * GH2_AS + m] = v.w;
    }
    __syncthreads();

    float acc[4][4];
#pragma unroll
    for (int r = 0; r < 4; r++)
#pragma unroll
        for (int s = 0; s < 4; s++) acc[r][s] = 0.f;
#pragma unroll 4
    for (int k = 0; k < 128; k++) {
        float4 a4 = *reinterpret_cast<const float4*>(&as[k * GH2_AS + ty * 4]);
        float4 w4 = *reinterpret_cast<const float4*>(&rs[k * GH2_RS + tx * 4]);
        float a[4] = {a4.x, a4.y, a4.z, a4.w};
        float w[4] = {w4.x, w4.y, w4.z, w4.w};
#pragma unroll
        for (int r = 0; r < 4; r++)
#pragma unroll
            for (int s = 0; s < 4; s++)
                acc[r][s] = fmaf(a[r], w[s], acc[r][s]);
    }
    float bv[4];
#pragma unroll
    for (int s = 0; s < 4; s++) bv[s] = bias1[tx * 4 + s];
#pragma unroll
    for (int r = 0; r < 4; r++) {
        int m = m0 + ty * 4 + r;
        if (m >= N_CNT) continue;
        float4 ag = *reinterpret_cast<const float4*>(&g_agg1[(size_t)m * H2 + tx * 4]);
        float v0 = fmaxf(acc[r][0] + bv[0] + ag.x, 0.f);
        float v1 = fmaxf(acc[r][1] + bv[1] + ag.y, 0.f);
        float v2 = fmaxf(acc[r][2] + bv[2] + ag.z, 0.f);
        float v3 = fmaxf(acc[r][3] + bv[3] + ag.w, 0.f);
        *reinterpret_cast<float4*>(&g_h2[(size_t)m * H2 + tx * 4]) =
            make_float4(v0, v1, v2, v3);
    }
}

// ---------------- launch 4: gemm_p2 (fp16 out) -------------------------------
#define GP2_HS 68
#define GP2_BS 172
#define GP2_SMEM ((64 * GP2_HS + 64 * GP2_BS) * 4)

__global__ __launch_bounds__(256, 2)
void gemm_p2() {
    extern __shared__ float s3[];
    float* h2t = s3;
    float* b2s = s3 + 64 * GP2_HS;
    int tid = threadIdx.x;
    int tx = tid & 15, ty = tid >> 4;
    int m0 = blockIdx.x * 64;

    for (int i = tid; i < 1024; i += 256) {
        int m = i >> 4, k4 = (i & 15) * 4;
        float4 v = (m0 + m < N_CNT)
            ? *reinterpret_cast<const float4*>(&g_h2[(size_t)(m0 + m) * H2 + k4])
            : make_float4(0.f, 0.f, 0.f, 0.f);
        h2t[(k4 + 0) * GP2_HS + m] = v.x;
        h2t[(k4 + 1) * GP2_HS + m] = v.y;
        h2t[(k4 + 2) * GP2_HS + m] = v.z;
        h2t[(k4 + 3) * GP2_HS + m] = v.w;
    }
    for (int i = tid; i < H2 * NB2; i += 256) {
        int k = i / NB2, c = i - k * NB2;
        b2s[k * GP2_BS + c] = g_B2[i];
    }
    __syncthreads();

#pragma unroll
    for (int p = 0; p < 3; p++) {
        int c0 = p * 64 + tx * 4;
        if (c0 >= NB2) break;
        float acc[4][4];
#pragma unroll
        for (int r = 0; r < 4; r++)
#pragma unroll
            for (int s = 0; s < 4; s++) acc[r][s] = 0.f;
#pragma unroll 4
        for (int k = 0; k < 64; k++) {
            float4 a4 = *reinterpret_cast<const float4*>(&h2t[k * GP2_HS + ty * 4]);
            float4 b4 = *reinterpret_cast<const float4*>(&b2s[k * GP2_BS + c0]);
            float a[4] = {a4.x, a4.y, a4.z, a4.w};
            float b[4] = {b4.x, b4.y, b4.z, b4.w};
#pragma unroll
            for (int r = 0; r < 4; r++)
#pragma unroll
                for (int s = 0; s < 4; s++)
                    acc[r][s] = fmaf(a[r], b[s], acc[r][s]);
        }
#pragma unroll
        for (int r = 0; r < 4; r++) {
            int m = m0 + ty * 4 + r;
            if (m >= N_CNT) continue;
            __half* dst = &g_P2[(size_t)m * NB2 + c0];
            if (c0 + 3 < NB2) {
                *reinterpret_cast<__half2*>(dst) =
                    __floats2half2_rn(acc[r][0], acc[r][1]);
                *reinterpret_cast<__half2*>(dst + 2) =
                    __floats2half2_rn(acc[r][2], acc[r][3]);
            } else {
#pragma unroll
                for (int s = 0; s < 4; s++)
                    if (c0 + s < NB2) dst[s] = __float2half_rn(acc[r][s]);
            }
        }
    }
}

// ---------------- launch 5: edge pass 2 (fp16, half2, 5 thr/edge) ------------
__global__ void edge_pass2(const float* __restrict__ ea) {
    int t = blockIdx.x * blockDim.x + threadIdx.x;
    if (t >= E_CNT * 5) return;
    int e = t / 5, c2 = (t - (t / 5) * 5) * 2;
    int s = g_src[e], d = g_dst[e];
    const __half* Prow = g_P2 + (size_t)s * NB2;
    float2 acc;
    {
        __half2 h = *reinterpret_cast<const __half2*>(Prow + EDIM * C_OUT + c2);
        acc = __half22float2(h);
    }
    const float* eav = ea + (size_t)e * EDIM;
#pragma unroll
    for (int k = 0; k < EDIM; k++) {
        float w = eav[k];
        __half2 h = *reinterpret_cast<const __half2*>(Prow + k * C_OUT + c2);
        float2 p = __half22float2(h);
        acc.x = fmaf(w, p.x, acc.x);
        acc.y = fmaf(w, p.y, acc.y);
    }
    float* dst = &g_agg2[(size_t)d * C_OUT + c2];
    atomicAdd(dst + 0, acc.x);
    atomicAdd(dst + 1, acc.y);
}

// ---------------- launch 6: final --------------------------------------------
__global__ void final_kernel(const float* __restrict__ root2,
                             const float* __restrict__ bias2,
                             float* __restrict__ out) {
    int n = blockIdx.x * blockDim.x + threadIdx.x;
    if (n >= N_CNT) return;
    float z[C_OUT];
#pragma unroll
    for (int c = 0; c < C_OUT; c++) z[c] = g_agg2[(size_t)n * C_OUT + c] + bias2[c];
    const float* hrow = g_h2 + (size_t)n * H2;
    for (int i = 0; i < H2; i++) {
        float hv = hrow[i];
#pragma unroll
        for (int c = 0; c < C_OUT; c++)
            z[c] = fmaf(hv, root2[i * C_OUT + c], z[c]);
    }
    float m = z[0];
#pragma unroll
    for (int c = 1; c < C_OUT; c++) m = fmaxf(m, z[c]);
    float sum = 0.f;
#pragma unroll
    for (int c = 0; c < C_OUT; c++) sum += expf(z[c] - m);
    float lse = m + logf(sum);
#pragma unroll
    for (int c = 0; c < C_OUT; c++) out[(size_t)n * C_OUT + c] = z[c] - lse;
}

// ---------------- launch -----------------------------------------------------
extern "C" void kernel_launch(void* const* d_in, const int* in_sizes, int n_in,
                              void* d_out, int out_size) {
    const float* x     = (const float*)d_in[0];
    const float* ea    = (const float*)d_in[1];
    const void*  eidx  = d_in[2];
    const float* W1    = (const float*)d_in[3];
    const float* b1    = (const float*)d_in[4];
    const float* We1   = (const float*)d_in[5];
    const float* be1   = (const float*)d_in[6];
    const float* root1 = (const float*)d_in[7];
    const float* bias1 = (const float*)d_in[8];
    const float* We2   = (const float*)d_in[9];
    const float* be2   = (const float*)d_in[10];
    const float* root2 = (const float*)d_in[11];
    const float* bias2 = (const float*)d_in[12];
    float* out = (float*)d_out;

    cudaFuncSetAttribute(fused_front, cudaFuncAttributeMaxDynamicSharedMemorySize,
                         GH_SMEM);
    cudaFuncSetAttribute(mma_gemm_p1, cudaFuncAttributeMaxDynamicSharedMemorySize,
                         MMA_SMEM);
    cudaFuncSetAttribute(gemm_h2, cudaFuncAttributeMaxDynamicSharedMemorySize,
                         GH2_SMEM);
    cudaFuncSetAttribute(gemm_p2, cudaFuncAttributeMaxDynamicSharedMemorySize,
                         GP2_SMEM);

    dim3 blk(256);
    // launch 0: fused front (gemm_h blocks + prep blocks)
    fused_front<<<GH_BLOCKS + PR_BLOCKS, blk, GH_SMEM>>>(x, W1, b1, eidx,
                                                         We1, be1, We2, be2);
    // launch 1
    {
        dim3 grid(NPAD / 128, MPAD / 128);
        mma_gemm_p1<<<grid, blk, MMA_SMEM>>>();
    }
    // launch 2
    edge_pass1<<<(E_CNT + 15) / 16, 256>>>(ea);
    // launch 3
    gemm_h2<<<(N_CNT + 63) / 64, blk, GH2_SMEM>>>(root1, bias1);
    // launch 4
    gemm_p2<<<(N_CNT + 63) / 64, blk, GP2_SMEM>>>();
    // launch 5
    edge_pass2<<<(E_CNT * 5 + 255) / 256, 256>>>(ea);
    // launch 6
    final_kernel<<<(N_CNT + 255) / 256, 256>>>(root2, bias2, out);
}

// round 17
// speedup vs baseline: 1.7008x; 1.0240x over previous
#include <cuda_runtime.h>
#include <cuda_bf16.h>
#include <cuda_fp16.h>
#include <math.h>
#include <stdint.h>

#define N_CNT 10000
#define E_CNT 30000
#define D_IN 64
#define EDIM 16
#define H1 128
#define H2 64
#define C_OUT 10

#define NB1 1088
#define NB2 170

#define MPAD 10112  // 79*128
#define NPAD 1152   // 9*128
#define KSPLIT 128  // single fp16 term: Ah x Bh

// ---------------- scratch ----------------------------------------------------
__device__ int   g_src[E_CNT];
__device__ int   g_dst[E_CNT];
__device__ float g_B2[H2 * NB2];
__device__ float g_h [N_CNT * H1];
__device__ __half g_Ab[(size_t)MPAD * KSPLIT];
__device__ __half g_Bb[(size_t)NPAD * KSPLIT];
__device__ __half g_P1[(size_t)N_CNT * NB1];
__device__ float g_agg1[N_CNT * H2];
__device__ float g_h2 [N_CNT * H2];
__device__ __half g_P2[(size_t)N_CNT * NB2];
__device__ float g_agg2[N_CNT * C_OUT];

// ---------------- helpers ----------------------------------------------------
__device__ __forceinline__ uint32_t smem_u32(const void* p) {
    uint32_t a;
    asm("{ .reg .u64 t; cvta.to.shared.u64 t, %1; cvt.u32.u64 %0, t; }"
        : "=r"(a) : "l"(p));
    return a;
}
__device__ __forceinline__ void ldmat_x4(uint32_t& r0, uint32_t& r1,
                                         uint32_t& r2, uint32_t& r3, uint32_t a) {
    asm volatile("ldmatrix.sync.aligned.m8n8.x4.shared.b16 {%0,%1,%2,%3}, [%4];"
                 : "=r"(r0), "=r"(r1), "=r"(r2), "=r"(r3) : "r"(a));
}
__device__ __forceinline__ void mma_f16(float* c, const uint32_t* a,
                                        const uint32_t* b) {
    asm volatile(
        "mma.sync.aligned.m16n8k16.row.col.f32.f16.f16.f32 "
        "{%0,%1,%2,%3}, {%4,%5,%6,%7}, {%8,%9}, {%0,%1,%2,%3};"
        : "+f"(c[0]), "+f"(c[1]), "+f"(c[2]), "+f"(c[3])
        : "r"(a[0]), "r"(a[1]), "r"(a[2]), "r"(a[3]), "r"(b[0]), "r"(b[1]));
}
__device__ __forceinline__ void cp16(uint32_t dst, const void* src) {
    asm volatile("cp.async.cg.shared.global [%0], [%1], 16;"
                 :: "r"(dst), "l"(src));
}
#define CP_COMMIT() asm volatile("cp.async.commit_group;" ::: "memory")
#define CP_WAIT0()  asm volatile("cp.async.wait_group 0;" ::: "memory")

// ---------------- launch 0: fused front = gemm_h blocks + prep blocks --------
#define GH_BLOCKS (MPAD / 64)           // 158
#define PR_O1 (E_CNT)
#define PR_O2 (PR_O1 + NPAD * H1)
#define PR_O3 (PR_O2 + H2 * NB2)
#define PR_O4 (PR_O3 + N_CNT * H2)
#define PR_TOT (PR_O4 + N_CNT * C_OUT)
#define PR_BLOCKS ((PR_TOT + 255) / 256)

#define HPAD_W 132
#define HPAD_A 68
#define GH_SMEM ((64 * HPAD_W + 64 * HPAD_A) * 4)

__global__ __launch_bounds__(256, 2)
void fused_front(const float* __restrict__ x, const float* __restrict__ W1,
                 const float* __restrict__ b1, const void* eidx,
                 const float* __restrict__ We1, const float* __restrict__ be1,
                 const float* __restrict__ We2, const float* __restrict__ be2) {
    if (blockIdx.x >= GH_BLOCKS) {
        int idx = (blockIdx.x - GH_BLOCKS) * blockDim.x + threadIdx.x;
        if (idx >= PR_TOT) return;
        if (idx < PR_O1) {
            const int* p = (const int*)eidx;
            bool is64 = true;
#pragma unroll
            for (int j = 0; j < 8; j++) is64 &= (p[2 * j + 1] == 0);
            if (is64) {
                const long long* q = (const long long*)eidx;
                g_src[idx] = (int)q[idx];
                g_dst[idx] = (int)q[E_CNT + idx];
            } else {
                g_src[idx] = p[idx];
                g_dst[idx] = p[E_CNT + idx];
            }
        } else if (idx < PR_O2) {
            int t = idx - PR_O1;
            int n = t / H1, k = t - n * H1;
            float v = 0.f;
            if (n < EDIM * H2) {
                int ke = n >> 6, o = n & 63;
                v = We1[(size_t)ke * (H1 * H2) + k * H2 + o];
            } else if (n < NB1) {
                v = be1[(size_t)k * H2 + (n - EDIM * H2)];
            }
            g_Bb[(size_t)n * KSPLIT + k] = __float2half_rn(v);
        } else if (idx < PR_O3) {
            int t = idx - PR_O2;
            int i = t / NB2, col = t - i * NB2;
            float v;
            if (col < EDIM * C_OUT) {
                int k = col / C_OUT, c = col - k * C_OUT;
                v = We2[(size_t)k * (H2 * C_OUT) + i * C_OUT + c];
            } else {
                v = be2[(size_t)i * C_OUT + (col - EDIM * C_OUT)];
            }
            g_B2[t] = v;
        } else if (idx < PR_O4) {
            g_agg1[idx - PR_O3] = 0.f;
        } else {
            g_agg2[idx - PR_O4] = 0.f;
        }
        return;
    }

    extern __shared__ float fsm[];
    float* Ws = fsm;
    float* As = fsm + 64 * HPAD_W;
    int tid = threadIdx.x;
    int tx = tid & 31, ty = tid >> 5;
    int m0 = blockIdx.x * 64;

    for (int i = tid; i < 2048; i += 256) {
        int k = i >> 5, n4 = (i & 31) * 4;
        float4 v = *reinterpret_cast<const float4*>(&W1[k * H1 + n4]);
        *reinterpret_cast<float4*>(&Ws[k * HPAD_W + n4]) = v;
    }
    for (int i = tid; i < 1024; i += 256) {
        int m = i >> 4, k4 = (i & 15) * 4;
        float4 v = (m0 + m < N_CNT)
            ? *reinterpret_cast<const float4*>(&x[(size_t)(m0 + m) * D_IN + k4])
            : make_float4(0.f, 0.f, 0.f, 0.f);
        As[(k4 + 0) * HPAD_A + m] = v.x;
        As[(k4 + 1) * HPAD_A + m] = v.y;
        As[(k4 + 2) * HPAD_A + m] = v.z;
        As[(k4 + 3) * HPAD_A + m] = v.w;
    }
    __syncthreads();

    float acc[8][4];
#pragma unroll
    for (int r = 0; r < 8; r++)
#pragma unroll
        for (int s = 0; s < 4; s++) acc[r][s] = 0.f;

#pragma unroll 4
    for (int k = 0; k < 64; k++) {
        float4 a0 = *reinterpret_cast<const float4*>(&As[k * HPAD_A + ty * 8]);
        float4 a1 = *reinterpret_cast<const float4*>(&As[k * HPAD_A + ty * 8 + 4]);
        float4 w  = *reinterpret_cast<const float4*>(&Ws[k * HPAD_W + tx * 4]);
        float a[8] = {a0.x, a0.y, a0.z, a0.w, a1.x, a1.y, a1.z, a1.w};
        float ww[4] = {w.x, w.y, w.z, w.w};
#pragma unroll
        for (int r = 0; r < 8; r++)
#pragma unroll
            for (int s = 0; s < 4; s++)
                acc[r][s] = fmaf(a[r], ww[s], acc[r][s]);
    }

    float bv[4];
#pragma unroll
    for (int s = 0; s < 4; s++) bv[s] = b1[tx * 4 + s];

#pragma unroll
    for (int r = 0; r < 8; r++) {
        int m = m0 + ty * 8 + r;
        float v[4];
#pragma unroll
        for (int s = 0; s < 4; s++) v[s] = fmaxf(acc[r][s] + bv[s], 0.f);
        if (m < N_CNT)
            *reinterpret_cast<float4*>(&g_h[(size_t)m * H1 + tx * 4]) =
                make_float4(v[0], v[1], v[2], v[3]);
        __half ah[4];
#pragma unroll
        for (int s = 0; s < 4; s++) ah[s] = __float2half_rn(v[s]);
        uint32_t hi0 = ((uint32_t)__half_as_ushort(ah[1]) << 16) |
                       __half_as_ushort(ah[0]);
        uint32_t hi1 = ((uint32_t)__half_as_ushort(ah[3]) << 16) |
                       __half_as_ushort(ah[2]);
        *reinterpret_cast<uint2*>(&g_Ab[(size_t)m * KSPLIT + tx * 4]) =
            make_uint2(hi0, hi1);
    }
}

// ---------------- launch 1: mma fp16 GEMM, K=128 single stage ----------------
#define SSTR 136
#define MMA_SMEM (2 * 128 * SSTR * 2)

__global__ __launch_bounds__(256, 2)
void mma_gemm_p1() {
    extern __shared__ __half sm[];
    __half* As = sm;
    __half* Bs = sm + 128 * SSTR;

    int tid = threadIdx.x;
    int wid = tid >> 5, lane = tid & 31;
    int row0 = blockIdx.y * 128;
    int col0 = blockIdx.x * 128;
    int wm0 = (wid >> 2) * 64;
    int wn0 = (wid & 3) * 32;

    int lrow = tid >> 1;
    int lq   = (tid & 1) * 8;
    const char* Ag = (const char*)(g_Ab) + (size_t)(row0 + lrow) * (KSPLIT * 2);
    const char* Bg = (const char*)(g_Bb) + (size_t)(col0 + lrow) * (KSPLIT * 2);
    uint32_t As_base = smem_u32(As);
    uint32_t Bs_base = smem_u32(Bs);
    uint32_t a_st = As_base + (uint32_t)(lrow * SSTR + lq * 8) * 2;
    uint32_t b_st = Bs_base + (uint32_t)(lrow * SSTR + lq * 8) * 2;

#pragma unroll
    for (int t = 0; t < 8; t++) {
        cp16(a_st + t * 16, Ag + (lq + t) * 16);
        cp16(b_st + t * 16, Bg + (lq + t) * 16);
    }
    CP_COMMIT();

    float acc[4][4][4];
#pragma unroll
    for (int i = 0; i < 4; i++)
#pragma unroll
        for (int j = 0; j < 4; j++)
#pragma unroll
            for (int q = 0; q < 4; q++) acc[i][j][q] = 0.f;

    int a_r = wm0 + (lane & 7) + ((lane >> 3) & 1) * 8;
    int a_c = ((lane >> 4) & 1) * 8;
    int b_r = wn0 + (lane & 7) + ((lane >> 4) & 1) * 8;
    int b_c = ((lane >> 3) & 1) * 8;

    CP_WAIT0();
    __syncthreads();

#pragma unroll
    for (int ks = 0; ks < 8; ks++) {
        int k0 = ks * 16;
        uint32_t afr[4][4], bfr[4][2];
#pragma unroll
        for (int i = 0; i < 4; i++) {
            uint32_t addr = As_base + (uint32_t)((a_r + i * 16) * SSTR + k0 + a_c) * 2;
            ldmat_x4(afr[i][0], afr[i][1], afr[i][2], afr[i][3], addr);
        }
#pragma unroll
        for (int jp = 0; jp < 2; jp++) {
            uint32_t addr = Bs_base + (uint32_t)((b_r + jp * 16) * SSTR + k0 + b_c) * 2;
            ldmat_x4(bfr[jp * 2][0], bfr[jp * 2][1],
                     bfr[jp * 2 + 1][0], bfr[jp * 2 + 1][1], addr);
        }
#pragma unroll
        for (int i = 0; i < 4; i++)
#pragma unroll
            for (int j = 0; j < 4; j++)
                mma_f16(acc[i][j], afr[i], bfr[j]);
    }

    int erow = lane >> 2;
    int ecol = (lane & 3) * 2;
#pragma unroll
    for (int i = 0; i < 4; i++) {
        int mg0 = row0 + wm0 + i * 16 + erow;
#pragma unroll
        for (int j = 0; j < 4; j++) {
            int ng = col0 + wn0 + j * 8 + ecol;
            if (ng >= NB1) continue;
            if (mg0 < N_CNT)
                *reinterpret_cast<__half2*>(&g_P1[(size_t)mg0 * NB1 + ng]) =
                    __floats2half2_rn(acc[i][j][0], acc[i][j][1]);
            if (mg0 + 8 < N_CNT)
                *reinterpret_cast<__half2*>(&g_P1[(size_t)(mg0 + 8) * NB1 + ng]) =
                    __floats2half2_rn(acc[i][j][2], acc[i][j][3]);
        }
    }
}

// ---------------- launch 2: edge pass 1 (fp16 gather, 16 thr/edge) -----------
__global__ void edge_pass1(const float* __restrict__ ea) {
    int le = threadIdx.x >> 4;
    int tq = threadIdx.x & 15;
    int e  = blockIdx.x * 16 + le;
    __shared__ float sea[16][17];
    if (e < E_CNT) sea[le][tq] = ea[(size_t)e * EDIM + tq];
    __syncthreads();
    if (e >= E_CNT) return;
    int s = g_src[e], d = g_dst[e];
    const __half* Prow = g_P1 + (size_t)s * NB1 + tq * 4;
    float4 acc;
    {
        uint2 raw = *reinterpret_cast<const uint2*>(Prow + EDIM * H2);
        __half2 h0 = *reinterpret_cast<__half2*>(&raw.x);
        __half2 h1 = *reinterpret_cast<__half2*>(&raw.y);
        float2 f0 = __half22float2(h0), f1 = __half22float2(h1);
        acc = make_float4(f0.x, f0.y, f1.x, f1.y);
    }
#pragma unroll
    for (int k = 0; k < EDIM; k++) {
        float w = sea[le][k];
        uint2 raw = *reinterpret_cast<const uint2*>(Prow + k * H2);
        __half2 h0 = *reinterpret_cast<__half2*>(&raw.x);
        __half2 h1 = *reinterpret_cast<__half2*>(&raw.y);
        float2 f0 = __half22float2(h0), f1 = __half22float2(h1);
        acc.x = fmaf(w, f0.x, acc.x);
        acc.y = fmaf(w, f0.y, acc.y);
        acc.z = fmaf(w, f1.x, acc.z);
        acc.w = fmaf(w, f1.y, acc.w);
    }
    float* dst = &g_agg1[(size_t)d * H2 + tq * 4];
    atomicAdd(dst + 0, acc.x);
    atomicAdd(dst + 1, acc.y);
    atomicAdd(dst + 2, acc.z);
    atomicAdd(dst + 3, acc.w);
}

// ---------------- launch 3: gemm_h2 (32-row tiles, grid 313) -----------------
#define GH2_RS 68
#define GH2_AS 36
#define GH2_SMEM ((128 * GH2_RS + 128 * GH2_AS) * 4)

__global__ __launch_bounds__(256, 2)
void gemm_h2(const float* __restrict__ root1, const float* __restrict__ bias1) {
    extern __shared__ float s2[];
    float* rs = s2;                   // root1 [k][n] 128x64
    float* as = s2 + 128 * GH2_RS;    // h^T   [k][m] 128x32
    int tid = threadIdx.x;
    int tx = tid & 15, ty = tid >> 4;
    int m0 = blockIdx.x * 32;

    for (int i = tid; i < 2048; i += 256) {
        int k = i >> 4, n4 = (i & 15) * 4;
        *reinterpret_cast<float4*>(&rs[k * GH2_RS + n4]) =
            *reinterpret_cast<const float4*>(&root1[k * H2 + n4]);
    }
    for (int i = tid; i < 1024; i += 256) {       // 32 rows x 32 float4
        int m = i >> 5, k4 = (i & 31) * 4;
        float4 v = (m0 + m < N_CNT)
            ? *reinterpret_cast<const float4*>(&g_h[(size_t)(m0 + m) * H1 + k4])
            : make_float4(0.f, 0.f, 0.f, 0.f);
        as[(k4 + 0) * GH2_AS + m] = v.x;
        as[(k4 + 1) * GH2_AS + m] = v.y;
        as[(k4 + 2) * GH2_AS + m] = v.z;
        as[(k4 + 3) * GH2_AS + m] = v.w;
    }
    __syncthreads();

    float acc[2][4];
#pragma unroll
    for (int r = 0; r < 2; r++)
#pragma unroll
        for (int s = 0; s < 4; s++) acc[r][s] = 0.f;
#pragma unroll 4
    for (int k = 0; k < 128; k++) {
        float2 a2 = *reinterpret_cast<const float2*>(&as[k * GH2_AS + ty * 2]);
        float4 w4 = *reinterpret_cast<const float4*>(&rs[k * GH2_RS + tx * 4]);
        float a[2] = {a2.x, a2.y};
        float w[4] = {w4.x, w4.y, w4.z, w4.w};
#pragma unroll
        for (int r = 0; r < 2; r++)
#pragma unroll
            for (int s = 0; s < 4; s++)
                acc[r][s] = fmaf(a[r], w[s], acc[r][s]);
    }
    float bv[4];
#pragma unroll
    for (int s = 0; s < 4; s++) bv[s] = bias1[tx * 4 + s];
#pragma unroll
    for (int r = 0; r < 2; r++) {
        int m = m0 + ty * 2 + r;
        if (m >= N_CNT) continue;
        float4 ag = *reinterpret_cast<const float4*>(&g_agg1[(size_t)m * H2 + tx * 4]);
        float v0 = fmaxf(acc[r][0] + bv[0] + ag.x, 0.f);
        float v1 = fmaxf(acc[r][1] + bv[1] + ag.y, 0.f);
        float v2 = fmaxf(acc[r][2] + bv[2] + ag.z, 0.f);
        float v3 = fmaxf(acc[r][3] + bv[3] + ag.w, 0.f);
        *reinterpret_cast<float4*>(&g_h2[(size_t)m * H2 + tx * 4]) =
            make_float4(v0, v1, v2, v3);
    }
}

// ---------------- launch 4: gemm_p2 (32-row tiles, fp16 out) -----------------
#define GP2_HS 36
#define GP2_BS 172
#define GP2_SMEM ((64 * GP2_HS + 64 * GP2_BS) * 4)

__global__ __launch_bounds__(256, 2)
void gemm_p2() {
    extern __shared__ float s3[];
    float* h2t = s3;                 // h2^T [k][m] 64x32
    float* b2s = s3 + 64 * GP2_HS;   // B2   [k][c] 64x170(+pad)
    int tid = threadIdx.x;
    int tx = tid & 15, ty = tid >> 4;
    int m0 = blockIdx.x * 32;

    for (int i = tid; i < 512; i += 256) {        // 32 rows x 16 float4
        int m = i >> 4, k4 = (i & 15) * 4;
        float4 v = (m0 + m < N_CNT)
            ? *reinterpret_cast<const float4*>(&g_h2[(size_t)(m0 + m) * H2 + k4])
            : make_float4(0.f, 0.f, 0.f, 0.f);
        h2t[(k4 + 0) * GP2_HS + m] = v.x;
        h2t[(k4 + 1) * GP2_HS + m] = v.y;
        h2t[(k4 + 2) * GP2_HS + m] = v.z;
        h2t[(k4 + 3) * GP2_HS + m] = v.w;
    }
    for (int i = tid; i < H2 * NB2; i += 256) {
        int k = i / NB2, c = i - k * NB2;
        b2s[k * GP2_BS + c] = g_B2[i];
    }
    __syncthreads();

#pragma unroll
    for (int p = 0; p < 3; p++) {
        int c0 = p * 64 + tx * 4;
        if (c0 >= NB2) break;
        float acc[2][4];
#pragma unroll
        for (int r = 0; r < 2; r++)
#pragma unroll
            for (int s = 0; s < 4; s++) acc[r][s] = 0.f;
#pragma unroll 4
        for (int k = 0; k < 64; k++) {
            float2 a2 = *reinterpret_cast<const float2*>(&h2t[k * GP2_HS + ty * 2]);
            float4 b4 = *reinterpret_cast<const float4*>(&b2s[k * GP2_BS + c0]);
            float a[2] = {a2.x, a2.y};
            float b[4] = {b4.x, b4.y, b4.z, b4.w};
#pragma unroll
            for (int r = 0; r < 2; r++)
#pragma unroll
                for (int s = 0; s < 4; s++)
                    acc[r][s] = fmaf(a[r], b[s], acc[r][s]);
        }
#pragma unroll
        for (int r = 0; r < 2; r++) {
            int m = m0 + ty * 2 + r;
            if (m >= N_CNT) continue;
            __half* dst = &g_P2[(size_t)m * NB2 + c0];
            if (c0 + 3 < NB2) {
                *reinterpret_cast<__half2*>(dst) =
                    __floats2half2_rn(acc[r][0], acc[r][1]);
                *reinterpret_cast<__half2*>(dst + 2) =
                    __floats2half2_rn(acc[r][2], acc[r][3]);
            } else {
#pragma unroll
                for (int s = 0; s < 4; s++)
                    if (c0 + s < NB2) dst[s] = __float2half_rn(acc[r][s]);
            }
        }
    }
}

// ---------------- launch 5: edge pass 2 (fp16, half2, 5 thr/edge) ------------
__global__ void edge_pass2(const float* __restrict__ ea) {
    int t = blockIdx.x * blockDim.x + threadIdx.x;
    if (t >= E_CNT * 5) return;
    int e = t / 5, c2 = (t - (t / 5) * 5) * 2;
    int s = g_src[e], d = g_dst[e];
    const __half* Prow = g_P2 + (size_t)s * NB2;
    float2 acc;
    {
        __half2 h = *reinterpret_cast<const __half2*>(Prow + EDIM * C_OUT + c2);
        acc = __half22float2(h);
    }
    const float* eav = ea + (size_t)e * EDIM;
#pragma unroll
    for (int k = 0; k < EDIM; k++) {
        float w = eav[k];
        __half2 h = *reinterpret_cast<const __half2*>(Prow + k * C_OUT + c2);
        float2 p = __half22float2(h);
        acc.x = fmaf(w, p.x, acc.x);
        acc.y = fmaf(w, p.y, acc.y);
    }
    float* dst = &g_agg2[(size_t)d * C_OUT + c2];
    atomicAdd(dst + 0, acc.x);
    atomicAdd(dst + 1, acc.y);
}

// ---------------- launch 6: final --------------------------------------------
__global__ void final_kernel(const float* __restrict__ root2,
                             const float* __restrict__ bias2,
                             float* __restrict__ out) {
    int n = blockIdx.x * blockDim.x + threadIdx.x;
    if (n >= N_CNT) return;
    float z[C_OUT];
#pragma unroll
    for (int c = 0; c < C_OUT; c++) z[c] = g_agg2[(size_t)n * C_OUT + c] + bias2[c];
    const float* hrow = g_h2 + (size_t)n * H2;
    for (int i = 0; i < H2; i++) {
        float hv = hrow[i];
#pragma unroll
        for (int c = 0; c < C_OUT; c++)
            z[c] = fmaf(hv, root2[i * C_OUT + c], z[c]);
    }
    float m = z[0];
#pragma unroll
    for (int c = 1; c < C_OUT; c++) m = fmaxf(m, z[c]);
    float sum = 0.f;
#pragma unroll
    for (int c = 0; c < C_OUT; c++) sum += expf(z[c] - m);
    float lse = m + logf(sum);
#pragma unroll
    for (int c = 0; c < C_OUT; c++) out[(size_t)n * C_OUT + c] = z[c] - lse;
}

// ---------------- launch -----------------------------------------------------
extern "C" void kernel_launch(void* const* d_in, const int* in_sizes, int n_in,
                              void* d_out, int out_size) {
    const float* x     = (const float*)d_in[0];
    const float* ea    = (const float*)d_in[1];
    const void*  eidx  = d_in[2];
    const float* W1    = (const float*)d_in[3];
    const float* b1    = (const float*)d_in[4];
    const float* We1   = (const float*)d_in[5];
    const float* be1   = (const float*)d_in[6];
    const float* root1 = (const float*)d_in[7];
    const float* bias1 = (const float*)d_in[8];
    const float* We2   = (const float*)d_in[9];
    const float* be2   = (const float*)d_in[10];
    const float* root2 = (const float*)d_in[11];
    const float* bias2 = (const float*)d_in[12];
    float* out = (float*)d_out;

    cudaFuncSetAttribute(fused_front, cudaFuncAttributeMaxDynamicSharedMemorySize,
                         GH_SMEM);
    cudaFuncSetAttribute(mma_gemm_p1, cudaFuncAttributeMaxDynamicSharedMemorySize,
                         MMA_SMEM);
    cudaFuncSetAttribute(gemm_h2, cudaFuncAttributeMaxDynamicSharedMemorySize,
                         GH2_SMEM);
    cudaFuncSetAttribute(gemm_p2, cudaFuncAttributeMaxDynamicSharedMemorySize,
                         GP2_SMEM);

    dim3 blk(256);
    fused_front<<<GH_BLOCKS + PR_BLOCKS, blk, GH_SMEM>>>(x, W1, b1, eidx,
                                                         We1, be1, We2, be2);
    {
        dim3 grid(NPAD / 128, MPAD / 128);
        mma_gemm_p1<<<grid, blk, MMA_SMEM>>>();
    }
    edge_pass1<<<(E_CNT + 15) / 16, 256>>>(ea);
    gemm_h2<<<(N_CNT + 31) / 32, blk, GH2_SMEM>>>(root1, bias1);
    gemm_p2<<<(N_CNT + 31) / 32, blk, GP2_SMEM>>>();
    edge_pass2<<<(E_CNT * 5 + 255) / 256, 256>>>(ea);
    final_kernel<<<(N_CNT + 255) / 256, 256>>>(root2, bias2, out);
}